// round 7
// baseline (speedup 1.0000x reference)
#include <cuda_runtime.h>
#include <math.h>
#include <stdint.h>

#define HIDDEN 768
#define NHEADS 12
#define HD 64
#define WIN 14
#define TOK 196                 // WIN*WIN
#define BATCH 256
#define MTOK (BATCH * TOK)      // 50176
#define NQKV (3 * HIDDEN)       // 2304

// Scratch (allocation-free rule: __device__ globals)
__device__ float g_qkv[(size_t)MTOK * NQKV];    // 50176 x 2304
__device__ float g_att[(size_t)MTOK * HIDDEN];  // 50176 x 768

__device__ __forceinline__ uint32_t f2tf32(float x) {
    uint32_t u;
    asm("cvt.rna.tf32.f32 %0, %1;" : "=r"(u) : "f"(x));
    return u;
}

__device__ __forceinline__ uint4 cvt4(float4 v) {
    return make_uint4(f2tf32(v.x), f2tf32(v.y), f2tf32(v.z), f2tf32(v.w));
}

__device__ __forceinline__ void mma_tf32(float c[4], const uint32_t a[4],
                                         const uint32_t b[2]) {
    asm("mma.sync.aligned.m16n8k8.row.col.f32.tf32.tf32.f32 "
        "{%0,%1,%2,%3}, {%4,%5,%6,%7}, {%8,%9}, {%0,%1,%2,%3};"
        : "+f"(c[0]), "+f"(c[1]), "+f"(c[2]), "+f"(c[3])
        : "r"(a[0]), "r"(a[1]), "r"(a[2]), "r"(a[3]), "r"(b[0]), "r"(b[1]));
}

// ---------------------------------------------------------------------------
// TF32 tensor-core GEMM:  C[M,N] = A[M,K] @ W[N,K]^T + bias[N]
// BM=BN=128, BK=16, 128 threads (4 warps), warp tile 64x64 (2x2 warp grid).
// Big warp tiles halve smem fragment re-reads vs 64x32 (A,B each read by
// only 2 warps) -> crossbar-bound inner loop gets ~40% fewer LDS cycles.
// Double-buffered smem, one __syncthreads per k-tile.
// ---------------------------------------------------------------------------
#define BKT 16
#define SSTR (BKT + 4)

__global__ __launch_bounds__(128, 2)
void gemm_tf32(const float* __restrict__ A, const float* __restrict__ W,
               const float* __restrict__ bias, float* __restrict__ C,
               int N, int K) {
    __shared__ uint32_t As[2][128][SSTR];
    __shared__ uint32_t Bs[2][128][SSTR];

    const int bm = blockIdx.y * 128;
    const int bn = blockIdx.x * 128;
    const int tid = threadIdx.x;
    const int warp = tid >> 5;
    const int lane = tid & 31;
    const int g = lane >> 2;
    const int tg = lane & 3;
    const int wm = (warp >> 1) * 64;   // warp m-offset (0 or 64)
    const int wn = (warp & 1) * 64;    // warp n-offset (0 or 64)

    float acc[4][8][4];
#pragma unroll
    for (int im = 0; im < 4; im++)
#pragma unroll
        for (int in = 0; in < 8; in++)
#pragma unroll
            for (int q = 0; q < 4; q++) acc[im][in][q] = 0.f;

    // Loader: thread t stages full 16-k row t of A and of W
    const float* Ap = A + (size_t)(bm + tid) * K;
    const float* Wp = W + (size_t)(bn + tid) * K;

    float4 a0 = *(const float4*)(Ap + 0);
    float4 a1 = *(const float4*)(Ap + 4);
    float4 a2 = *(const float4*)(Ap + 8);
    float4 a3 = *(const float4*)(Ap + 12);
    float4 w0 = *(const float4*)(Wp + 0);
    float4 w1 = *(const float4*)(Wp + 4);
    float4 w2 = *(const float4*)(Wp + 8);
    float4 w3 = *(const float4*)(Wp + 12);

    // Prologue: stage tile 0 into buffer 0
    *(uint4*)&As[0][tid][0]  = cvt4(a0);
    *(uint4*)&As[0][tid][4]  = cvt4(a1);
    *(uint4*)&As[0][tid][8]  = cvt4(a2);
    *(uint4*)&As[0][tid][12] = cvt4(a3);
    *(uint4*)&Bs[0][tid][0]  = cvt4(w0);
    *(uint4*)&Bs[0][tid][4]  = cvt4(w1);
    *(uint4*)&Bs[0][tid][8]  = cvt4(w2);
    *(uint4*)&Bs[0][tid][12] = cvt4(w3);
    __syncthreads();

    int p = 0;
    for (int k0 = 0; k0 < K; k0 += BKT, p ^= 1) {
        const bool more = (k0 + BKT) < K;
        if (more) {  // issue next-tile loads before MMA: latency hidden
            const float* An = Ap + k0 + BKT;
            const float* Wn = Wp + k0 + BKT;
            a0 = *(const float4*)(An + 0);
            a1 = *(const float4*)(An + 4);
            a2 = *(const float4*)(An + 8);
            a3 = *(const float4*)(An + 12);
            w0 = *(const float4*)(Wn + 0);
            w1 = *(const float4*)(Wn + 4);
            w2 = *(const float4*)(Wn + 8);
            w3 = *(const float4*)(Wn + 12);
        }

#pragma unroll
        for (int ks = 0; ks < 2; ks++) {
            const int kb = ks * 8;
            uint32_t af[4][4], bf[8][2];
#pragma unroll
            for (int im = 0; im < 4; im++) {
                const int r = wm + im * 16 + g;
                af[im][0] = As[p][r][kb + tg];
                af[im][1] = As[p][r + 8][kb + tg];
                af[im][2] = As[p][r][kb + tg + 4];
                af[im][3] = As[p][r + 8][kb + tg + 4];
            }
#pragma unroll
            for (int in = 0; in < 8; in++) {
                const int nr = wn + in * 8 + g;
                bf[in][0] = Bs[p][nr][kb + tg];
                bf[in][1] = Bs[p][nr][kb + tg + 4];
            }
#pragma unroll
            for (int im = 0; im < 4; im++)
#pragma unroll
                for (int in = 0; in < 8; in++)
                    mma_tf32(acc[im][in], af[im], bf[in]);
        }

        if (more) {  // stage next tile into the other buffer
            *(uint4*)&As[p ^ 1][tid][0]  = cvt4(a0);
            *(uint4*)&As[p ^ 1][tid][4]  = cvt4(a1);
            *(uint4*)&As[p ^ 1][tid][8]  = cvt4(a2);
            *(uint4*)&As[p ^ 1][tid][12] = cvt4(a3);
            *(uint4*)&Bs[p ^ 1][tid][0]  = cvt4(w0);
            *(uint4*)&Bs[p ^ 1][tid][4]  = cvt4(w1);
            *(uint4*)&Bs[p ^ 1][tid][8]  = cvt4(w2);
            *(uint4*)&Bs[p ^ 1][tid][12] = cvt4(w3);
        }
        __syncthreads();
    }

    // Epilogue: add bias, write fp32 (float2 stores)
#pragma unroll
    for (int im = 0; im < 4; im++) {
        const int row = bm + wm + im * 16 + g;
#pragma unroll
        for (int in = 0; in < 8; in++) {
            const int col = bn + wn + in * 8 + 2 * tg;
            const float b0 = bias[col], b1 = bias[col + 1];
            float* Cr = C + (size_t)row * N + col;
            *(float2*)Cr = make_float2(acc[im][in][0] + b0,
                                       acc[im][in][1] + b1);
            float* Cr8 = C + (size_t)(row + 8) * N + col;
            *(float2*)Cr8 = make_float2(acc[im][in][2] + b0,
                                        acc[im][in][3] + b1);
        }
    }
}

// ---------------------------------------------------------------------------
// Tensor-core attention: one block per (batch*head), 512 threads = 16 warps.
// (unchanged this round)
// ---------------------------------------------------------------------------
#define KP 224
#define QT 64
#define QS 68
#define VS2 228

#define KS_OFF  0
#define QP_OFF  (KS_OFF + KP * QS)
#define VT_OFF  (QP_OFF + QT * QS)
#define SS_OFF  (VT_OFF + 64 * VS2)
#define RH_OFF  (SS_OFF + 64 * VS2)
#define RW_OFF  (RH_OFF + 27 * 68)
#define RLH_OFF (RW_OFF + 27 * 68)
#define RLW_OFF (RLH_OFF + 64 * 16)
#define SIV_OFF (RLW_OFF + 64 * 16)
#define ATT_SMEM_FLOATS (SIV_OFF + 64)
#define ATT_SMEM_BYTES  (ATT_SMEM_FLOATS * 4)

__global__ __launch_bounds__(512, 1)
void attn_mma(const float* __restrict__ qkv,
              const float* __restrict__ rel_pos_h,
              const float* __restrict__ rel_pos_w,
              float* __restrict__ att_out) {
    extern __shared__ __align__(16) float sm[];
    float*    Ks   = sm + KS_OFF;
    float*    Qp   = sm + QP_OFF;
    float*    Vt   = sm + VT_OFF;
    float*    Ssm  = sm + SS_OFF;
    float*    Rh   = sm + RH_OFF;
    float*    Rw   = sm + RW_OFF;
    float*    RelH = sm + RLH_OFF;
    float*    RelW = sm + RLW_OFF;
    float*    Sinv = sm + SIV_OFF;
    uint32_t* Ksu  = (uint32_t*)Ks;
    uint32_t* Qpu  = (uint32_t*)Qp;
    uint32_t* Vtu  = (uint32_t*)Vt;
    uint32_t* Ssu  = (uint32_t*)Ssm;

    const int bh = blockIdx.x;
    const int b = bh / NHEADS;
    const int head = bh % NHEADS;
    const int tid = threadIdx.x;
    const int warp = tid >> 5;
    const int lane = tid & 31;
    const int g = lane >> 2;
    const int tg = lane & 3;
    const int mt = warp >> 2;
    const int quar = warp & 3;

    const float* base = qkv + (size_t)b * TOK * NQKV + head * HD;

    for (int i = tid; i < KP * 64; i += 512) {
        const int t = i >> 6, d = i & 63;
        const float kv = (t < TOK) ? base[(size_t)t * NQKV + HIDDEN + d] : 0.f;
        Ksu[t * QS + d] = f2tf32(kv);
    }
    for (int i = tid; i < 27 * 64; i += 512) {
        const int r = i >> 6, c = i & 63;
        Rh[r * 68 + c] = rel_pos_h[i];
        Rw[r * 68 + c] = rel_pos_w[i];
    }

    // Stage V^T via 64x65 transpose chunks through Qp (conflict-free)
    {
        float* Tmp = Qp;
        for (int c = 0; c < 4; c++) {
            const int t0 = c * 56;
            for (int i = tid; i < 56 * 64; i += 512) {
                const int tt = i >> 6, d = i & 63;
                const int t = t0 + tt;
                Tmp[tt * 65 + d] =
                    (t < TOK) ? base[(size_t)t * NQKV + 2 * HIDDEN + d] : 0.f;
            }
            __syncthreads();
            for (int i = tid; i < 56 * 64; i += 512) {
                const int d = i / 56, tt = i % 56;
                Vtu[d * VS2 + t0 + tt] = f2tf32(Tmp[tt * 65 + d]);
            }
            __syncthreads();
        }
    }

    const float scale = 0.125f;

    for (int pass = 0; pass < 4; pass++) {
        const int q0 = pass * QT;

        for (int i = tid; i < QT * 64; i += 512) {
            const int q = i >> 6, d = i & 63;
            const int qt = q0 + q;
            const float v = (qt < TOK) ? base[(size_t)qt * NQKV + d] : 0.f;
            Qpu[q * QS + d] = f2tf32(v);
        }
        __syncthreads();

#pragma unroll
        for (int it = 0; it < 4; it++) {
            const int i = tid + 512 * it;
            if (i < 64 * 28) {
                const int q = i / 28, c = i % 28;
                const int qt = q0 + q;
                if (qt < TOK) {
                    const int qh = qt / WIN, qw = qt % WIN;
                    const float* R;
                    int rr;
                    if (c < 14) { rr = qh - c + 13;        R = Rh; }
                    else        { rr = qw - (c - 14) + 13; R = Rw; }
                    const float2* qp2 = (const float2*)(Qp + q * QS);
                    const float2* r2  = (const float2*)(R + rr * 68);
                    float acc = 0.f;
#pragma unroll
                    for (int u = 0; u < 32; u++) {
                        const float2 a = qp2[u], bb = r2[u];
                        acc += a.x * bb.x + a.y * bb.y;
                    }
                    if (c < 14) RelH[q * 16 + c]      = acc;
                    else        RelW[q * 16 + c - 14] = acc;
                }
            }
        }

        float s[7][4];
#pragma unroll
        for (int j = 0; j < 7; j++)
#pragma unroll
            for (int q = 0; q < 4; q++) s[j][q] = 0.f;

#pragma unroll
        for (int ks = 0; ks < 8; ks++) {
            const int kb = ks * 8;
            uint32_t af[4];
            const int r = mt * 16 + g;
            af[0] = Qpu[r * QS + kb + tg];
            af[1] = Qpu[(r + 8) * QS + kb + tg];
            af[2] = Qpu[r * QS + kb + tg + 4];
            af[3] = Qpu[(r + 8) * QS + kb + tg + 4];
#pragma unroll
            for (int j = 0; j < 7; j++) {
                const int kn = (quar * 7 + j) * 8;
                uint32_t bf[2];
                bf[0] = Ksu[(kn + g) * QS + kb + tg];
                bf[1] = Ksu[(kn + g) * QS + kb + tg + 4];
                mma_tf32(s[j], af, bf);
            }
        }
#pragma unroll
        for (int j = 0; j < 7; j++) {
            const int kn = (quar * 7 + j) * 8;
            const int r = mt * 16 + g;
            *(float2*)&Ssm[r * VS2 + kn + 2 * tg] =
                make_float2(s[j][0], s[j][1]);
            *(float2*)&Ssm[(r + 8) * VS2 + kn + 2 * tg] =
                make_float2(s[j][2], s[j][3]);
        }
        __syncthreads();

#pragma unroll
        for (int rr8 = 0; rr8 < 4; rr8++) {
            const int r = warp + rr8 * 16;
            const int qt = q0 + r;
            if (qt < TOK) {
                float sv[7];
                float m = -1e30f;
#pragma unroll
                for (int j = 0; j < 7; j++) {
                    const int k = lane + 32 * j;
                    if (k < TOK) {
                        sv[j] = Ssm[r * VS2 + k] * scale
                              + RelH[r * 16 + k / WIN]
                              + RelW[r * 16 + k % WIN];
                    } else sv[j] = -1e30f;
                    m = fmaxf(m, sv[j]);
                }
#pragma unroll
                for (int off = 16; off > 0; off >>= 1)
                    m = fmaxf(m, __shfl_xor_sync(0xffffffffu, m, off));
                float p[7], sum = 0.f;
#pragma unroll
                for (int j = 0; j < 7; j++) {
                    const int k = lane + 32 * j;
                    p[j] = (k < TOK) ? __expf(sv[j] - m) : 0.f;
                    sum += p[j];
                }
#pragma unroll
                for (int off = 16; off > 0; off >>= 1)
                    sum += __shfl_xor_sync(0xffffffffu, sum, off);
                if (lane == 0) Sinv[r] = 1.f / sum;
#pragma unroll
                for (int j = 0; j < 7; j++)
                    Ssm[r * VS2 + lane + 32 * j] = p[j];
            }
        }
        __syncthreads();

        float o[2][4];
#pragma unroll
        for (int jn = 0; jn < 2; jn++)
#pragma unroll
            for (int q = 0; q < 4; q++) o[jn][q] = 0.f;

#pragma unroll
        for (int ks = 0; ks < 28; ks++) {
            const int kb = ks * 8;
            uint32_t af[4];
            const int r = mt * 16 + g;
            af[0] = Ssu[r * VS2 + kb + tg];
            af[1] = Ssu[(r + 8) * VS2 + kb + tg];
            af[2] = Ssu[r * VS2 + kb + tg + 4];
            af[3] = Ssu[(r + 8) * VS2 + kb + tg + 4];
#pragma unroll
            for (int jn = 0; jn < 2; jn++) {
                const int nd = quar * 16 + jn * 8 + g;
                uint32_t bf[2];
                bf[0] = Vtu[nd * VS2 + kb + tg];
                bf[1] = Vtu[nd * VS2 + kb + tg + 4];
                mma_tf32(o[jn], af, bf);
            }
        }

        {
            const int qt0 = q0 + mt * 16 + g;
            const int qt1 = qt0 + 8;
            const float inv0 = (qt0 < TOK) ? Sinv[mt * 16 + g] : 0.f;
            const float inv1 = (qt1 < TOK) ? Sinv[mt * 16 + g + 8] : 0.f;
#pragma unroll
            for (int jn = 0; jn < 2; jn++) {
                const int d = quar * 16 + jn * 8 + 2 * tg;
                if (qt0 < TOK) {
                    float* o0 = att_out + (size_t)(b * TOK + qt0) * HIDDEN
                              + head * HD + d;
                    *(float2*)o0 = make_float2(o[jn][0] * inv0, o[jn][1] * inv0);
                }
                if (qt1 < TOK) {
                    float* o1 = att_out + (size_t)(b * TOK + qt1) * HIDDEN
                              + head * HD + d;
                    *(float2*)o1 = make_float2(o[jn][2] * inv1, o[jn][3] * inv1);
                }
            }
        }
        __syncthreads();
    }
}

// ---------------------------------------------------------------------------
extern "C" void kernel_launch(void* const* d_in, const int* in_sizes, int n_in,
                              void* d_out, int out_size) {
    const float* hidden = (const float*)d_in[0];
    const float* qkv_w  = (const float*)d_in[1];
    const float* qkv_b  = (const float*)d_in[2];
    const float* proj_w = (const float*)d_in[3];
    const float* proj_b = (const float*)d_in[4];
    const float* rel_h  = (const float*)d_in[5];
    const float* rel_w  = (const float*)d_in[6];
    float* out = (float*)d_out;

    void* p_qkv = nullptr;
    void* p_att = nullptr;
    cudaGetSymbolAddress(&p_qkv, g_qkv);
    cudaGetSymbolAddress(&p_att, g_att);

    cudaFuncSetAttribute(attn_mma,
                         cudaFuncAttributeMaxDynamicSharedMemorySize,
                         ATT_SMEM_BYTES);

    // 1) QKV projection (tf32 tensor cores, 64x64 warp tiles)
    gemm_tf32<<<dim3(NQKV / 128, MTOK / 128), 128>>>(
        hidden, qkv_w, qkv_b, (float*)p_qkv, NQKV, HIDDEN);

    // 2) Attention (tf32 tensor cores, 16 warps/block)
    attn_mma<<<BATCH * NHEADS, 512, ATT_SMEM_BYTES>>>(
        (const float*)p_qkv, rel_h, rel_w, (float*)p_att);

    // 3) Output projection (tf32 tensor cores, 64x64 warp tiles)
    gemm_tf32<<<dim3(HIDDEN / 128, MTOK / 128), 128>>>(
        (const float*)p_att, proj_w, proj_b, out, HIDDEN, HIDDEN);
}

// round 10
// speedup vs baseline: 1.2505x; 1.2505x over previous
#include <cuda_runtime.h>
#include <math.h>
#include <stdint.h>

#define HIDDEN 768
#define NHEADS 12
#define HD 64
#define WIN 14
#define TOK 196                 // WIN*WIN
#define BATCH 256
#define MTOK (BATCH * TOK)      // 50176
#define NQKV (3 * HIDDEN)       // 2304

// Scratch (allocation-free rule: __device__ globals)
__device__ float g_qkv[(size_t)MTOK * NQKV];    // 50176 x 2304
__device__ float g_att[(size_t)MTOK * HIDDEN];  // 50176 x 768

__device__ __forceinline__ uint32_t f2tf32(float x) {
    uint32_t u;
    asm("cvt.rna.tf32.f32 %0, %1;" : "=r"(u) : "f"(x));
    return u;
}

__device__ __forceinline__ uint4 cvt4(float4 v) {
    return make_uint4(f2tf32(v.x), f2tf32(v.y), f2tf32(v.z), f2tf32(v.w));
}

__device__ __forceinline__ void mma_tf32(float c[4], const uint32_t a[4],
                                         const uint32_t b[2]) {
    asm("mma.sync.aligned.m16n8k8.row.col.f32.tf32.tf32.f32 "
        "{%0,%1,%2,%3}, {%4,%5,%6,%7}, {%8,%9}, {%0,%1,%2,%3};"
        : "+f"(c[0]), "+f"(c[1]), "+f"(c[2]), "+f"(c[3])
        : "r"(a[0]), "r"(a[1]), "r"(a[2]), "r"(a[3]), "r"(b[0]), "r"(b[1]));
}

// ---------------------------------------------------------------------------
// TF32 tensor-core GEMM (R4 config):  C[M,N] = A[M,K] @ W[N,K]^T + bias[N]
// BM=BN=128, BK=16, 256 threads (8 warps), warp tile 64x32.
// Double-buffered smem, one __syncthreads per k-tile.
// ---------------------------------------------------------------------------
#define BKT 16
#define SSTR (BKT + 4)

__global__ __launch_bounds__(256, 2)
void gemm_tf32(const float* __restrict__ A, const float* __restrict__ W,
               const float* __restrict__ bias, float* __restrict__ C,
               int N, int K) {
    __shared__ uint32_t As[2][128][SSTR];
    __shared__ uint32_t Bs[2][128][SSTR];

    const int bm = blockIdx.y * 128;
    const int bn = blockIdx.x * 128;
    const int tid = threadIdx.x;
    const int warp = tid >> 5;
    const int lane = tid & 31;
    const int g = lane >> 2;
    const int tg = lane & 3;
    const int wm = (warp >> 2) * 64;
    const int wn = (warp & 3) * 32;

    const int r0 = tid >> 2;
    const int c0 = (tid & 3) * 4;
    const int r1 = r0 + 64;

    float acc[4][4][4];
#pragma unroll
    for (int im = 0; im < 4; im++)
#pragma unroll
        for (int in = 0; in < 4; in++)
#pragma unroll
            for (int q = 0; q < 4; q++) acc[im][in][q] = 0.f;

    const float* Ap0 = A + (size_t)(bm + r0) * K + c0;
    const float* Ap1 = A + (size_t)(bm + r1) * K + c0;
    const float* Wp0 = W + (size_t)(bn + r0) * K + c0;
    const float* Wp1 = W + (size_t)(bn + r1) * K + c0;

    float4 av0 = *(const float4*)Ap0;
    float4 av1 = *(const float4*)Ap1;
    float4 wv0 = *(const float4*)Wp0;
    float4 wv1 = *(const float4*)Wp1;

    *(uint4*)&As[0][r0][c0] = cvt4(av0);
    *(uint4*)&As[0][r1][c0] = cvt4(av1);
    *(uint4*)&Bs[0][r0][c0] = cvt4(wv0);
    *(uint4*)&Bs[0][r1][c0] = cvt4(wv1);
    __syncthreads();

    int p = 0;
    for (int k0 = 0; k0 < K; k0 += BKT, p ^= 1) {
        const bool more = (k0 + BKT) < K;
        if (more) {
            av0 = *(const float4*)(Ap0 + k0 + BKT);
            av1 = *(const float4*)(Ap1 + k0 + BKT);
            wv0 = *(const float4*)(Wp0 + k0 + BKT);
            wv1 = *(const float4*)(Wp1 + k0 + BKT);
        }

#pragma unroll
        for (int ks = 0; ks < 2; ks++) {
            const int kb = ks * 8;
            uint32_t af[4][4], bf[4][2];
#pragma unroll
            for (int im = 0; im < 4; im++) {
                const int r = wm + im * 16 + g;
                af[im][0] = As[p][r][kb + tg];
                af[im][1] = As[p][r + 8][kb + tg];
                af[im][2] = As[p][r][kb + tg + 4];
                af[im][3] = As[p][r + 8][kb + tg + 4];
            }
#pragma unroll
            for (int in = 0; in < 4; in++) {
                const int nr = wn + in * 8 + g;
                bf[in][0] = Bs[p][nr][kb + tg];
                bf[in][1] = Bs[p][nr][kb + tg + 4];
            }
#pragma unroll
            for (int im = 0; im < 4; im++)
#pragma unroll
                for (int in = 0; in < 4; in++)
                    mma_tf32(acc[im][in], af[im], bf[in]);
        }

        if (more) {
            *(uint4*)&As[p ^ 1][r0][c0] = cvt4(av0);
            *(uint4*)&As[p ^ 1][r1][c0] = cvt4(av1);
            *(uint4*)&Bs[p ^ 1][r0][c0] = cvt4(wv0);
            *(uint4*)&Bs[p ^ 1][r1][c0] = cvt4(wv1);
        }
        __syncthreads();
    }

#pragma unroll
    for (int im = 0; im < 4; im++) {
        const int row = bm + wm + im * 16 + g;
#pragma unroll
        for (int in = 0; in < 4; in++) {
            const int col = bn + wn + in * 8 + 2 * tg;
            const float b0 = bias[col], b1 = bias[col + 1];
            float* Cr = C + (size_t)row * N + col;
            *(float2*)Cr = make_float2(acc[im][in][0] + b0,
                                       acc[im][in][1] + b1);
            float* Cr8 = C + (size_t)(row + 8) * N + col;
            *(float2*)Cr8 = make_float2(acc[im][in][2] + b0,
                                        acc[im][in][3] + b1);
        }
    }
}

// ---------------------------------------------------------------------------
// Tensor-core attention: one block per (batch*head), 512 threads = 16 warps.
// Rel-pos bias now via MMA: E_h = Q @ Rh^T, E_w = Q @ Rw^T (64x32x64, folded
// into the QK^T k-loop so Q fragments are loaded once), then softmax does
// two table lookups per key instead of 28 smem dot-products per query.
// ---------------------------------------------------------------------------
#define KP 224
#define QT 64
#define QS 68
#define VS2 228
#define ES 32

#define KS_OFF  0                            // 224*68 = 15232
#define QP_OFF  (KS_OFF + KP * QS)           // 64*68  = 4352 (also 64x65 tmp)
#define VT_OFF  (QP_OFF + QT * QS)           // 64*228 = 14592
#define SS_OFF  (VT_OFF + 64 * VS2)          // 64*228 = 14592
#define RHU_OFF (SS_OFF + 64 * VS2)          // 27*68  = 1836
#define RWU_OFF (RHU_OFF + 27 * QS)          // 27*68  = 1836
#define EH_OFF  (RWU_OFF + 27 * QS)          // 64*32  = 2048
#define EW_OFF  (EH_OFF + 64 * ES)           // 64*32  = 2048
#define SIV_OFF (EW_OFF + 64 * ES)           // 64
#define ATT_SMEM_FLOATS (SIV_OFF + 64)
#define ATT_SMEM_BYTES  (ATT_SMEM_FLOATS * 4)

__global__ __launch_bounds__(512, 1)
void attn_mma(const float* __restrict__ qkv,
              const float* __restrict__ rel_pos_h,
              const float* __restrict__ rel_pos_w,
              float* __restrict__ att_out) {
    extern __shared__ __align__(16) float sm[];
    float*    Ks   = sm + KS_OFF;
    float*    Qp   = sm + QP_OFF;
    float*    Vt   = sm + VT_OFF;
    float*    Ssm  = sm + SS_OFF;
    float*    Eh   = sm + EH_OFF;
    float*    Ew   = sm + EW_OFF;
    float*    Sinv = sm + SIV_OFF;
    uint32_t* Ksu  = (uint32_t*)Ks;
    uint32_t* Qpu  = (uint32_t*)Qp;
    uint32_t* Vtu  = (uint32_t*)Vt;
    uint32_t* Ssu  = (uint32_t*)Ssm;
    uint32_t* RHUu = (uint32_t*)(sm + RHU_OFF);
    uint32_t* RWUu = (uint32_t*)(sm + RWU_OFF);

    const int bh = blockIdx.x;
    const int b = bh / NHEADS;
    const int head = bh % NHEADS;
    const int tid = threadIdx.x;
    const int warp = tid >> 5;
    const int lane = tid & 31;
    const int g = lane >> 2;
    const int tg = lane & 3;
    const int mt = warp >> 2;
    const int quar = warp & 3;

    const float* base = qkv + (size_t)b * TOK * NQKV + head * HD;

    // Stage K (row-major tf32, zero-padded) + rel-pos tables as tf32
    for (int i = tid; i < KP * 64; i += 512) {
        const int t = i >> 6, d = i & 63;
        const float kv = (t < TOK) ? base[(size_t)t * NQKV + HIDDEN + d] : 0.f;
        Ksu[t * QS + d] = f2tf32(kv);
    }
    for (int i = tid; i < 27 * 64; i += 512) {
        const int r = i >> 6, c = i & 63;
        RHUu[r * QS + c] = f2tf32(rel_pos_h[i]);
        RWUu[r * QS + c] = f2tf32(rel_pos_w[i]);
    }

    // Stage V^T via 64x65 transpose chunks through Qp (conflict-free)
    {
        float* Tmp = Qp;
        for (int c = 0; c < 4; c++) {
            const int t0 = c * 56;
            for (int i = tid; i < 56 * 64; i += 512) {
                const int tt = i >> 6, d = i & 63;
                const int t = t0 + tt;
                Tmp[tt * 65 + d] =
                    (t < TOK) ? base[(size_t)t * NQKV + 2 * HIDDEN + d] : 0.f;
            }
            __syncthreads();
            for (int i = tid; i < 56 * 64; i += 512) {
                const int d = i / 56, tt = i % 56;
                Vtu[d * VS2 + t0 + tt] = f2tf32(Tmp[tt * 65 + d]);
            }
            __syncthreads();
        }
    }

    const float scale = 0.125f;

    // Per-lane key decompositions (constant across passes)
    int khi[7], kwi[7];
#pragma unroll
    for (int j = 0; j < 7; j++) {
        const int k = lane + 32 * j;
        khi[j] = k / WIN;
        kwi[j] = k - WIN * khi[j];
    }

    for (int pass = 0; pass < 4; pass++) {
        const int q0 = pass * QT;

        for (int i = tid; i < QT * 64; i += 512) {
            const int q = i >> 6, d = i & 63;
            const int qt = q0 + q;
            const float v = (qt < TOK) ? base[(size_t)qt * NQKV + d] : 0.f;
            Qpu[q * QS + d] = f2tf32(v);
        }
        __syncthreads();

        // QK^T (7 key-tiles/warp) + rel-table GEMM (2 tiles/warp), shared af.
        // quar<2 -> Eh tiles (cols quar*16 + jr*8), quar>=2 -> Ew.
        const uint32_t* Ru = (quar < 2) ? RHUu : RWUu;
        const int ecb = (quar & 1) * 16;

        float s[7][4];
        float er[2][4];
#pragma unroll
        for (int j = 0; j < 7; j++)
#pragma unroll
            for (int q = 0; q < 4; q++) s[j][q] = 0.f;
#pragma unroll
        for (int jr = 0; jr < 2; jr++)
#pragma unroll
            for (int q = 0; q < 4; q++) er[jr][q] = 0.f;

#pragma unroll
        for (int ks = 0; ks < 8; ks++) {
            const int kb = ks * 8;
            uint32_t af[4];
            const int r = mt * 16 + g;
            af[0] = Qpu[r * QS + kb + tg];
            af[1] = Qpu[(r + 8) * QS + kb + tg];
            af[2] = Qpu[r * QS + kb + tg + 4];
            af[3] = Qpu[(r + 8) * QS + kb + tg + 4];
#pragma unroll
            for (int j = 0; j < 7; j++) {
                const int kn = (quar * 7 + j) * 8;
                uint32_t bf[2];
                bf[0] = Ksu[(kn + g) * QS + kb + tg];
                bf[1] = Ksu[(kn + g) * QS + kb + tg + 4];
                mma_tf32(s[j], af, bf);
            }
#pragma unroll
            for (int jr = 0; jr < 2; jr++) {
                const int rj = ecb + jr * 8 + g;  // table row (over-read of
                uint32_t bf[2];                    // rows 27..31 only pollutes
                bf[0] = Ru[rj * QS + kb + tg];     // unused E cols)
                bf[1] = Ru[rj * QS + kb + tg + 4];
                mma_tf32(er[jr], af, bf);
            }
        }
#pragma unroll
        for (int j = 0; j < 7; j++) {
            const int kn = (quar * 7 + j) * 8;
            const int r = mt * 16 + g;
            *(float2*)&Ssm[r * VS2 + kn + 2 * tg] =
                make_float2(s[j][0], s[j][1]);
            *(float2*)&Ssm[(r + 8) * VS2 + kn + 2 * tg] =
                make_float2(s[j][2], s[j][3]);
        }
        {
            float* Edst = (quar < 2) ? Eh : Ew;
            const int r = mt * 16 + g;
#pragma unroll
            for (int jr = 0; jr < 2; jr++) {
                const int col = ecb + jr * 8 + 2 * tg;
                *(float2*)&Edst[r * ES + col] =
                    make_float2(er[jr][0], er[jr][1]);
                *(float2*)&Edst[(r + 8) * ES + col] =
                    make_float2(er[jr][2], er[jr][3]);
            }
        }
        __syncthreads();

        // Softmax: 4 rows per warp; bias via E-table lookups
#pragma unroll
        for (int rr8 = 0; rr8 < 4; rr8++) {
            const int r = warp + rr8 * 16;
            const int qt = q0 + r;
            if (qt < TOK) {
                const int qh = qt / WIN, qw = qt - WIN * (qt / WIN);
                const float* EhR = Eh + r * ES;
                const float* EwR = Ew + r * ES;
                float sv[7];
                float m = -1e30f;
#pragma unroll
                for (int j = 0; j < 7; j++) {
                    const int k = lane + 32 * j;
                    if (k < TOK) {
                        sv[j] = Ssm[r * VS2 + k] * scale
                              + EhR[qh - khi[j] + 13]
                              + EwR[qw - kwi[j] + 13];
                    } else sv[j] = -1e30f;
                    m = fmaxf(m, sv[j]);
                }
#pragma unroll
                for (int off = 16; off > 0; off >>= 1)
                    m = fmaxf(m, __shfl_xor_sync(0xffffffffu, m, off));
                float p[7], sum = 0.f;
#pragma unroll
                for (int j = 0; j < 7; j++) {
                    const int k = lane + 32 * j;
                    p[j] = (k < TOK) ? __expf(sv[j] - m) : 0.f;
                    sum += p[j];
                }
#pragma unroll
                for (int off = 16; off > 0; off >>= 1)
                    sum += __shfl_xor_sync(0xffffffffu, sum, off);
                if (lane == 0) Sinv[r] = 1.f / sum;
#pragma unroll
                for (int j = 0; j < 7; j++)
                    Ssm[r * VS2 + lane + 32 * j] = p[j];
            }
        }
        __syncthreads();

        // PV: 2 dim-tiles per warp over 28 k-tiles
        float o[2][4];
#pragma unroll
        for (int jn = 0; jn < 2; jn++)
#pragma unroll
            for (int q = 0; q < 4; q++) o[jn][q] = 0.f;

#pragma unroll
        for (int ks = 0; ks < 28; ks++) {
            const int kb = ks * 8;
            uint32_t af[4];
            const int r = mt * 16 + g;
            af[0] = Ssu[r * VS2 + kb + tg];
            af[1] = Ssu[(r + 8) * VS2 + kb + tg];
            af[2] = Ssu[r * VS2 + kb + tg + 4];
            af[3] = Ssu[(r + 8) * VS2 + kb + tg + 4];
#pragma unroll
            for (int jn = 0; jn < 2; jn++) {
                const int nd = quar * 16 + jn * 8 + g;
                uint32_t bf[2];
                bf[0] = Vtu[nd * VS2 + kb + tg];
                bf[1] = Vtu[nd * VS2 + kb + tg + 4];
                mma_tf32(o[jn], af, bf);
            }
        }

        {
            const int qt0 = q0 + mt * 16 + g;
            const int qt1 = qt0 + 8;
            const float inv0 = (qt0 < TOK) ? Sinv[mt * 16 + g] : 0.f;
            const float inv1 = (qt1 < TOK) ? Sinv[mt * 16 + g + 8] : 0.f;
#pragma unroll
            for (int jn = 0; jn < 2; jn++) {
                const int d = quar * 16 + jn * 8 + 2 * tg;
                if (qt0 < TOK) {
                    float* o0 = att_out + (size_t)(b * TOK + qt0) * HIDDEN
                              + head * HD + d;
                    *(float2*)o0 = make_float2(o[jn][0] * inv0, o[jn][1] * inv0);
                }
                if (qt1 < TOK) {
                    float* o1 = att_out + (size_t)(b * TOK + qt1) * HIDDEN
                              + head * HD + d;
                    *(float2*)o1 = make_float2(o[jn][2] * inv1, o[jn][3] * inv1);
                }
            }
        }
        __syncthreads();
    }
}

// ---------------------------------------------------------------------------
extern "C" void kernel_launch(void* const* d_in, const int* in_sizes, int n_in,
                              void* d_out, int out_size) {
    const float* hidden = (const float*)d_in[0];
    const float* qkv_w  = (const float*)d_in[1];
    const float* qkv_b  = (const float*)d_in[2];
    const float* proj_w = (const float*)d_in[3];
    const float* proj_b = (const float*)d_in[4];
    const float* rel_h  = (const float*)d_in[5];
    const float* rel_w  = (const float*)d_in[6];
    float* out = (float*)d_out;

    void* p_qkv = nullptr;
    void* p_att = nullptr;
    cudaGetSymbolAddress(&p_qkv, g_qkv);
    cudaGetSymbolAddress(&p_att, g_att);

    cudaFuncSetAttribute(attn_mma,
                         cudaFuncAttributeMaxDynamicSharedMemorySize,
                         ATT_SMEM_BYTES);

    // 1) QKV projection (tf32 tensor cores, R4 config)
    gemm_tf32<<<dim3(NQKV / 128, MTOK / 128), 256>>>(
        hidden, qkv_w, qkv_b, (float*)p_qkv, NQKV, HIDDEN);

    // 2) Attention (tf32 tensor cores, MMA rel-pos bias)
    attn_mma<<<BATCH * NHEADS, 512, ATT_SMEM_BYTES>>>(
        (const float*)p_qkv, rel_h, rel_w, (float*)p_att);

    // 3) Output projection (tf32 tensor cores, R4 config)
    gemm_tf32<<<dim3(HIDDEN / 128, MTOK / 128), 256>>>(
        (const float*)p_att, proj_w, proj_b, out, HIDDEN, HIDDEN);
}

// round 11
// speedup vs baseline: 1.4524x; 1.1614x over previous
#include <cuda_runtime.h>
#include <cuda_fp16.h>
#include <math.h>
#include <stdint.h>

#define HIDDEN 768
#define NHEADS 12
#define HD 64
#define WIN 14
#define TOK 196                 // WIN*WIN
#define BATCH 256
#define MTOK (BATCH * TOK)      // 50176
#define NQKV (3 * HIDDEN)       // 2304

// Scratch (allocation-free rule: __device__ globals)
__device__ float g_qkv[(size_t)MTOK * NQKV];    // 50176 x 2304
__device__ float g_att[(size_t)MTOK * HIDDEN];  // 50176 x 768

__device__ __forceinline__ uint32_t pk(float x, float y) {
    __half2 h = __floats2half2_rn(x, y);
    return *reinterpret_cast<uint32_t*>(&h);
}

__device__ __forceinline__ void mma_f16(float c[4], const uint32_t a[4],
                                        const uint32_t b[2]) {
    asm("mma.sync.aligned.m16n8k16.row.col.f32.f16.f16.f32 "
        "{%0,%1,%2,%3}, {%4,%5,%6,%7}, {%8,%9}, {%0,%1,%2,%3};"
        : "+f"(c[0]), "+f"(c[1]), "+f"(c[2]), "+f"(c[3])
        : "r"(a[0]), "r"(a[1]), "r"(a[2]), "r"(a[3]), "r"(b[0]), "r"(b[1]));
}

// ---------------------------------------------------------------------------
// FP16 tensor-core GEMM (fp32 accumulate):  C = A[M,K] @ W[N,K]^T + bias
// BM=BN=128, BK=32 (16 half2 words/row, row stride 20 words -> conflict-free
// 20g+tg fragment map). 256 threads, 8 warps, warp tile 64x32.
// Double-buffered smem, one __syncthreads per k-tile.
// ---------------------------------------------------------------------------
#define BKT 32
#define SW 20    // smem row stride in half2 words

__global__ __launch_bounds__(256, 2)
void gemm_f16(const float* __restrict__ A, const float* __restrict__ W,
              const float* __restrict__ bias, float* __restrict__ C,
              int N, int K) {
    __shared__ uint32_t As[2][128][SW];
    __shared__ uint32_t Bs[2][128][SW];

    const int bm = blockIdx.y * 128;
    const int bn = blockIdx.x * 128;
    const int tid = threadIdx.x;
    const int warp = tid >> 5;
    const int lane = tid & 31;
    const int g = lane >> 2;
    const int tg = lane & 3;
    const int wm = (warp >> 2) * 64;
    const int wn = (warp & 3) * 32;

    // Loader: thread covers rows r0 and r0+64, float cols fc..fc+7
    const int r0 = tid >> 2;
    const int r1 = r0 + 64;
    const int fc = (tid & 3) * 8;
    const int wc = (tid & 3) * 4;   // word col

    float acc[4][4][4];
#pragma unroll
    for (int im = 0; im < 4; im++)
#pragma unroll
        for (int in = 0; in < 4; in++)
#pragma unroll
            for (int q = 0; q < 4; q++) acc[im][in][q] = 0.f;

    const float* Ap0 = A + (size_t)(bm + r0) * K + fc;
    const float* Ap1 = A + (size_t)(bm + r1) * K + fc;
    const float* Wp0 = W + (size_t)(bn + r0) * K + fc;
    const float* Wp1 = W + (size_t)(bn + r1) * K + fc;

    float4 a00 = *(const float4*)(Ap0 + 0);
    float4 a01 = *(const float4*)(Ap0 + 4);
    float4 a10 = *(const float4*)(Ap1 + 0);
    float4 a11 = *(const float4*)(Ap1 + 4);
    float4 w00 = *(const float4*)(Wp0 + 0);
    float4 w01 = *(const float4*)(Wp0 + 4);
    float4 w10 = *(const float4*)(Wp1 + 0);
    float4 w11 = *(const float4*)(Wp1 + 4);

#define STAGE(buf)                                                          \
    do {                                                                    \
        *(uint4*)&As[buf][r0][wc] = make_uint4(pk(a00.x, a00.y),            \
            pk(a00.z, a00.w), pk(a01.x, a01.y), pk(a01.z, a01.w));          \
        *(uint4*)&As[buf][r1][wc] = make_uint4(pk(a10.x, a10.y),            \
            pk(a10.z, a10.w), pk(a11.x, a11.y), pk(a11.z, a11.w));          \
        *(uint4*)&Bs[buf][r0][wc] = make_uint4(pk(w00.x, w00.y),            \
            pk(w00.z, w00.w), pk(w01.x, w01.y), pk(w01.z, w01.w));          \
        *(uint4*)&Bs[buf][r1][wc] = make_uint4(pk(w10.x, w10.y),            \
            pk(w10.z, w10.w), pk(w11.x, w11.y), pk(w11.z, w11.w));          \
    } while (0)

    STAGE(0);
    __syncthreads();

    int p = 0;
    for (int k0 = 0; k0 < K; k0 += BKT, p ^= 1) {
        const bool more = (k0 + BKT) < K;
        if (more) {
            const int ko = k0 + BKT;
            a00 = *(const float4*)(Ap0 + ko);
            a01 = *(const float4*)(Ap0 + ko + 4);
            a10 = *(const float4*)(Ap1 + ko);
            a11 = *(const float4*)(Ap1 + ko + 4);
            w00 = *(const float4*)(Wp0 + ko);
            w01 = *(const float4*)(Wp0 + ko + 4);
            w10 = *(const float4*)(Wp1 + ko);
            w11 = *(const float4*)(Wp1 + ko + 4);
        }

#pragma unroll
        for (int ks = 0; ks < 2; ks++) {
            const int kb = ks * 8;
            uint32_t af[4][4], bf[4][2];
#pragma unroll
            for (int im = 0; im < 4; im++) {
                const int r = wm + im * 16 + g;
                af[im][0] = As[p][r][kb + tg];
                af[im][1] = As[p][r + 8][kb + tg];
                af[im][2] = As[p][r][kb + tg + 4];
                af[im][3] = As[p][r + 8][kb + tg + 4];
            }
#pragma unroll
            for (int in = 0; in < 4; in++) {
                const int nr = wn + in * 8 + g;
                bf[in][0] = Bs[p][nr][kb + tg];
                bf[in][1] = Bs[p][nr][kb + tg + 4];
            }
#pragma unroll
            for (int im = 0; im < 4; im++)
#pragma unroll
                for (int in = 0; in < 4; in++)
                    mma_f16(acc[im][in], af[im], bf[in]);
        }

        if (more) STAGE(p ^ 1);
        __syncthreads();
    }
#undef STAGE

#pragma unroll
    for (int im = 0; im < 4; im++) {
        const int row = bm + wm + im * 16 + g;
#pragma unroll
        for (int in = 0; in < 4; in++) {
            const int col = bn + wn + in * 8 + 2 * tg;
            const float b0 = bias[col], b1 = bias[col + 1];
            float* Cr = C + (size_t)row * N + col;
            *(float2*)Cr = make_float2(acc[im][in][0] + b0,
                                       acc[im][in][1] + b1);
            float* Cr8 = C + (size_t)(row + 8) * N + col;
            *(float2*)Cr8 = make_float2(acc[im][in][2] + b0,
                                        acc[im][in][3] + b1);
        }
    }
}

// ---------------------------------------------------------------------------
// FP16 tensor-core attention: one block per (batch*head), 512 thr, 16 warps.
// All operands (Q,K,V,P,rel tables) as half2 words; scores + E tables fp32;
// fp32 accumulate everywhere. Keys padded 196->224.
// Word strides: 36 (Q/K/R, 36%32=4) and 116 (V/P, 116%32=20): both give the
// conflict-free {s*g + tg} fragment bank map. Score stride 228 fp32.
// ---------------------------------------------------------------------------
#define KP 224
#define QT 64
#define KWS 36    // Q/K/R word stride
#define VWS 116   // V/P word stride
#define SSF 228   // score fp32 stride
#define ES 32

#define KS_OFF  0                          // 224*36 = 8064 words
#define QP_OFF  (KS_OFF + KP * KWS)        // 64*36  = 2304
#define VT_OFF  (QP_OFF + QT * KWS)        // 64*116 = 7424
#define SS_OFF  (VT_OFF + 64 * VWS)        // 64*228 = 14592 (fp32)
#define PB_OFF  (SS_OFF + 64 * SSF)        // 64*116 = 7424 (also V-transpose tmp)
#define RH_OFF  (PB_OFF + 64 * VWS)        // 32*36 = 1152
#define RW_OFF  (RH_OFF + 32 * KWS)        // 1152
#define EH_OFF  (RW_OFF + 32 * KWS)        // 64*32 fp32
#define EW_OFF  (EH_OFF + 64 * ES)
#define SIV_OFF (EW_OFF + 64 * ES)         // 64
#define ATT_SMEM_WORDS (SIV_OFF + 64)
#define ATT_SMEM_BYTES (ATT_SMEM_WORDS * 4)

__global__ __launch_bounds__(512, 1)
void attn_mma(const float* __restrict__ qkv,
              const float* __restrict__ rel_pos_h,
              const float* __restrict__ rel_pos_w,
              float* __restrict__ att_out) {
    extern __shared__ __align__(16) float sm[];
    uint32_t* Ksu = (uint32_t*)(sm + KS_OFF);
    uint32_t* Qpu = (uint32_t*)(sm + QP_OFF);
    uint32_t* Vtu = (uint32_t*)(sm + VT_OFF);
    float*    Ssm = sm + SS_OFF;
    uint32_t* Pbu = (uint32_t*)(sm + PB_OFF);
    __half*   Pbh = (__half*)Pbu;
    uint32_t* RHu = (uint32_t*)(sm + RH_OFF);
    uint32_t* RWu = (uint32_t*)(sm + RW_OFF);
    float*    Eh  = sm + EH_OFF;
    float*    Ew  = sm + EW_OFF;
    float*    Sinv = sm + SIV_OFF;

    const int bh = blockIdx.x;
    const int b = bh / NHEADS;
    const int head = bh % NHEADS;
    const int tid = threadIdx.x;
    const int warp = tid >> 5;
    const int lane = tid & 31;
    const int g = lane >> 2;
    const int tg = lane & 3;
    const int mt = warp >> 2;
    const int quar = warp & 3;

    const float* base = qkv + (size_t)b * TOK * NQKV + head * HD;

    // Stage K (half2 words, zero-padded) and rel tables (rows 27..31 zeroed)
    for (int i = tid; i < KP * 32; i += 512) {
        const int t = i >> 5, d2 = i & 31;
        float2 v = make_float2(0.f, 0.f);
        if (t < TOK)
            v = *(const float2*)(base + (size_t)t * NQKV + HIDDEN + 2 * d2);
        Ksu[t * KWS + d2] = pk(v.x, v.y);
    }
    for (int i = tid; i < 32 * 32; i += 512) {
        const int r = i >> 5, d2 = i & 31;
        float2 h = make_float2(0.f, 0.f), w = make_float2(0.f, 0.f);
        if (r < 27) {
            h = *(const float2*)(rel_pos_h + r * 64 + 2 * d2);
            w = *(const float2*)(rel_pos_w + r * 64 + 2 * d2);
        }
        RHu[r * KWS + d2] = pk(h.x, h.y);
        RWu[r * KWS + d2] = pk(w.x, w.y);
    }

    // Stage V^T via 56-token fp32 transpose chunks through the P buffer
    {
        float* Tmp = (float*)Pbu;  // 56*65 = 3640 floats <= 7424
        for (int c = 0; c < 4; c++) {
            const int t0 = c * 56;
            for (int i = tid; i < 56 * 64; i += 512) {
                const int tt = i >> 6, d = i & 63;
                const int t = t0 + tt;
                Tmp[tt * 65 + d] =
                    (t < TOK) ? base[(size_t)t * NQKV + 2 * HIDDEN + d] : 0.f;
            }
            __syncthreads();
            for (int i = tid; i < 64 * 28; i += 512) {
                const int d = i / 28, wt = i % 28;
                Vtu[d * VWS + c * 28 + wt] =
                    pk(Tmp[(2 * wt) * 65 + d], Tmp[(2 * wt + 1) * 65 + d]);
            }
            __syncthreads();
        }
    }

    const float scale = 0.125f;

    int khi[7], kwi[7];
#pragma unroll
    for (int j = 0; j < 7; j++) {
        const int k = lane + 32 * j;
        khi[j] = k / WIN;
        kwi[j] = k - WIN * khi[j];
    }

    for (int pass = 0; pass < 4; pass++) {
        const int q0 = pass * QT;

        for (int i = tid; i < QT * 32; i += 512) {
            const int q = i >> 5, d2 = i & 31;
            const int qt = q0 + q;
            float2 v = make_float2(0.f, 0.f);
            if (qt < TOK)
                v = *(const float2*)(base + (size_t)qt * NQKV + 2 * d2);
            Qpu[q * KWS + d2] = pk(v.x, v.y);
        }
        __syncthreads();

        // QK^T (7 key-tiles/warp) + rel-table MMA (2 tiles/warp), shared af
        const uint32_t* Ru = (quar < 2) ? RHu : RWu;
        const int ecb = (quar & 1) * 16;

        float s[7][4];
        float er[2][4];
#pragma unroll
        for (int j = 0; j < 7; j++)
#pragma unroll
            for (int q = 0; q < 4; q++) s[j][q] = 0.f;
#pragma unroll
        for (int jr = 0; jr < 2; jr++)
#pragma unroll
            for (int q = 0; q < 4; q++) er[jr][q] = 0.f;

#pragma unroll
        for (int ks = 0; ks < 4; ks++) {   // 64 dims = 4 x k16
            const int kb = ks * 8;
            uint32_t af[4];
            const int r = mt * 16 + g;
            af[0] = Qpu[r * KWS + kb + tg];
            af[1] = Qpu[(r + 8) * KWS + kb + tg];
            af[2] = Qpu[r * KWS + kb + tg + 4];
            af[3] = Qpu[(r + 8) * KWS + kb + tg + 4];
#pragma unroll
            for (int j = 0; j < 7; j++) {
                const int kn = (quar * 7 + j) * 8;
                uint32_t bf[2];
                bf[0] = Ksu[(kn + g) * KWS + kb + tg];
                bf[1] = Ksu[(kn + g) * KWS + kb + tg + 4];
                mma_f16(s[j], af, bf);
            }
#pragma unroll
            for (int jr = 0; jr < 2; jr++) {
                const int rj = ecb + jr * 8 + g;
                uint32_t bf[2];
                bf[0] = Ru[rj * KWS + kb + tg];
                bf[1] = Ru[rj * KWS + kb + tg + 4];
                mma_f16(er[jr], af, bf);
            }
        }
#pragma unroll
        for (int j = 0; j < 7; j++) {
            const int kn = (quar * 7 + j) * 8;
            const int r = mt * 16 + g;
            *(float2*)&Ssm[r * SSF + kn + 2 * tg] =
                make_float2(s[j][0], s[j][1]);
            *(float2*)&Ssm[(r + 8) * SSF + kn + 2 * tg] =
                make_float2(s[j][2], s[j][3]);
        }
        {
            float* Edst = (quar < 2) ? Eh : Ew;
            const int r = mt * 16 + g;
#pragma unroll
            for (int jr = 0; jr < 2; jr++) {
                const int col = ecb + jr * 8 + 2 * tg;
                *(float2*)&Edst[r * ES + col] =
                    make_float2(er[jr][0], er[jr][1]);
                *(float2*)&Edst[(r + 8) * ES + col] =
                    make_float2(er[jr][2], er[jr][3]);
            }
        }
        __syncthreads();

        // Softmax: 4 rows per warp; write P as halves
#pragma unroll
        for (int rr8 = 0; rr8 < 4; rr8++) {
            const int r = warp + rr8 * 16;
            const int qt = q0 + r;
            if (qt < TOK) {
                const int qh = qt / WIN, qw = qt - WIN * (qt / WIN);
                const float* EhR = Eh + r * ES;
                const float* EwR = Ew + r * ES;
                float sv[7];
                float m = -1e30f;
#pragma unroll
                for (int j = 0; j < 7; j++) {
                    const int k = lane + 32 * j;
                    if (k < TOK) {
                        sv[j] = Ssm[r * SSF + k] * scale
                              + EhR[qh - khi[j] + 13]
                              + EwR[qw - kwi[j] + 13];
                    } else sv[j] = -1e30f;
                    m = fmaxf(m, sv[j]);
                }
#pragma unroll
                for (int off = 16; off > 0; off >>= 1)
                    m = fmaxf(m, __shfl_xor_sync(0xffffffffu, m, off));
                float p[7], sum = 0.f;
#pragma unroll
                for (int j = 0; j < 7; j++) {
                    const int k = lane + 32 * j;
                    p[j] = (k < TOK) ? __expf(sv[j] - m) : 0.f;
                    sum += p[j];
                }
#pragma unroll
                for (int off = 16; off > 0; off >>= 1)
                    sum += __shfl_xor_sync(0xffffffffu, sum, off);
                if (lane == 0) Sinv[r] = 1.f / sum;
#pragma unroll
                for (int j = 0; j < 7; j++)
                    Pbh[r * (2 * VWS) + lane + 32 * j] = __float2half_rn(p[j]);
            }
        }
        __syncthreads();

        // PV: 2 dim-tiles per warp over 14 k16-chunks (224 keys)
        float o[2][4];
#pragma unroll
        for (int jn = 0; jn < 2; jn++)
#pragma unroll
            for (int q = 0; q < 4; q++) o[jn][q] = 0.f;

#pragma unroll
        for (int ks = 0; ks < 14; ks++) {
            const int kb = ks * 8;
            uint32_t af[4];
            const int r = mt * 16 + g;
            af[0] = Pbu[r * VWS + kb + tg];
            af[1] = Pbu[(r + 8) * VWS + kb + tg];
            af[2] = Pbu[r * VWS + kb + tg + 4];
            af[3] = Pbu[(r + 8) * VWS + kb + tg + 4];
#pragma unroll
            for (int jn = 0; jn < 2; jn++) {
                const int nd = quar * 16 + jn * 8 + g;
                uint32_t bf[2];
                bf[0] = Vtu[nd * VWS + kb + tg];
                bf[1] = Vtu[nd * VWS + kb + tg + 4];
                mma_f16(o[jn], af, bf);
            }
        }

        {
            const int qt0 = q0 + mt * 16 + g;
            const int qt1 = qt0 + 8;
            const float inv0 = (qt0 < TOK) ? Sinv[mt * 16 + g] : 0.f;
            const float inv1 = (qt1 < TOK) ? Sinv[mt * 16 + g + 8] : 0.f;
#pragma unroll
            for (int jn = 0; jn < 2; jn++) {
                const int d = quar * 16 + jn * 8 + 2 * tg;
                if (qt0 < TOK) {
                    float* o0 = att_out + (size_t)(b * TOK + qt0) * HIDDEN
                              + head * HD + d;
                    *(float2*)o0 = make_float2(o[jn][0] * inv0, o[jn][1] * inv0);
                }
                if (qt1 < TOK) {
                    float* o1 = att_out + (size_t)(b * TOK + qt1) * HIDDEN
                              + head * HD + d;
                    *(float2*)o1 = make_float2(o[jn][2] * inv1, o[jn][3] * inv1);
                }
            }
        }
        __syncthreads();
    }
}

// ---------------------------------------------------------------------------
extern "C" void kernel_launch(void* const* d_in, const int* in_sizes, int n_in,
                              void* d_out, int out_size) {
    const float* hidden = (const float*)d_in[0];
    const float* qkv_w  = (const float*)d_in[1];
    const float* qkv_b  = (const float*)d_in[2];
    const float* proj_w = (const float*)d_in[3];
    const float* proj_b = (const float*)d_in[4];
    const float* rel_h  = (const float*)d_in[5];
    const float* rel_w  = (const float*)d_in[6];
    float* out = (float*)d_out;

    void* p_qkv = nullptr;
    void* p_att = nullptr;
    cudaGetSymbolAddress(&p_qkv, g_qkv);
    cudaGetSymbolAddress(&p_att, g_att);

    cudaFuncSetAttribute(attn_mma,
                         cudaFuncAttributeMaxDynamicSharedMemorySize,
                         ATT_SMEM_BYTES);

    // 1) QKV projection (fp16 tensor cores, fp32 accumulate)
    gemm_f16<<<dim3(NQKV / 128, MTOK / 128), 256>>>(
        hidden, qkv_w, qkv_b, (float*)p_qkv, NQKV, HIDDEN);

    // 2) Attention (fp16 tensor cores, fp32 softmax/accumulate)
    attn_mma<<<BATCH * NHEADS, 512, ATT_SMEM_BYTES>>>(
        (const float*)p_qkv, rel_h, rel_w, (float*)p_att);

    // 3) Output projection (fp16 tensor cores, fp32 accumulate)
    gemm_f16<<<dim3(HIDDEN / 128, MTOK / 128), 256>>>(
        (const float*)p_att, proj_w, proj_b, out, HIDDEN, HIDDEN);
}

// round 14
// speedup vs baseline: 1.5660x; 1.0782x over previous
#include <cuda_runtime.h>
#include <cuda_fp16.h>
#include <math.h>
#include <stdint.h>

#define HIDDEN 768
#define NHEADS 12
#define HD 64
#define WIN 14
#define TOK 196                 // WIN*WIN
#define BATCH 256
#define MTOK (BATCH * TOK)      // 50176
#define NQKV (3 * HIDDEN)       // 2304

// Scratch (allocation-free rule: __device__ globals)
__device__ float g_qkv[(size_t)MTOK * NQKV];    // 50176 x 2304
__device__ float g_att[(size_t)MTOK * HIDDEN];  // 50176 x 768

__device__ __forceinline__ uint32_t pk(float x, float y) {
    __half2 h = __floats2half2_rn(x, y);
    return *reinterpret_cast<uint32_t*>(&h);
}

__device__ __forceinline__ void mma_f16(float c[4], const uint32_t a[4],
                                        const uint32_t b[2]) {
    asm("mma.sync.aligned.m16n8k16.row.col.f32.f16.f16.f32 "
        "{%0,%1,%2,%3}, {%4,%5,%6,%7}, {%8,%9}, {%0,%1,%2,%3};"
        : "+f"(c[0]), "+f"(c[1]), "+f"(c[2]), "+f"(c[3])
        : "r"(a[0]), "r"(a[1]), "r"(a[2]), "r"(a[3]), "r"(b[0]), "r"(b[1]));
}

// ---------------------------------------------------------------------------
// FP16 tensor-core GEMM (fp32 accumulate):  C = A[M,K] @ W[N,K]^T + bias
// BM=BN=128, BK=32 (16 half2 words/row, stride 20 -> conflict-free).
// 256 threads, 8 warps, warp tile 64x32. Double-buffered smem.  (R11 config)
// ---------------------------------------------------------------------------
#define BKT 32
#define SW 20    // smem row stride in half2 words

__global__ __launch_bounds__(256, 2)
void gemm_f16(const float* __restrict__ A, const float* __restrict__ W,
              const float* __restrict__ bias, float* __restrict__ C,
              int N, int K) {
    __shared__ uint32_t As[2][128][SW];
    __shared__ uint32_t Bs[2][128][SW];

    const int bm = blockIdx.y * 128;
    const int bn = blockIdx.x * 128;
    const int tid = threadIdx.x;
    const int warp = tid >> 5;
    const int lane = tid & 31;
    const int g = lane >> 2;
    const int tg = lane & 3;
    const int wm = (warp >> 2) * 64;
    const int wn = (warp & 3) * 32;

    const int r0 = tid >> 2;
    const int r1 = r0 + 64;
    const int fc = (tid & 3) * 8;
    const int wc = (tid & 3) * 4;

    float acc[4][4][4];
#pragma unroll
    for (int im = 0; im < 4; im++)
#pragma unroll
        for (int in = 0; in < 4; in++)
#pragma unroll
            for (int q = 0; q < 4; q++) acc[im][in][q] = 0.f;

    const float* Ap0 = A + (size_t)(bm + r0) * K + fc;
    const float* Ap1 = A + (size_t)(bm + r1) * K + fc;
    const float* Wp0 = W + (size_t)(bn + r0) * K + fc;
    const float* Wp1 = W + (size_t)(bn + r1) * K + fc;

    float4 a00 = *(const float4*)(Ap0 + 0);
    float4 a01 = *(const float4*)(Ap0 + 4);
    float4 a10 = *(const float4*)(Ap1 + 0);
    float4 a11 = *(const float4*)(Ap1 + 4);
    float4 w00 = *(const float4*)(Wp0 + 0);
    float4 w01 = *(const float4*)(Wp0 + 4);
    float4 w10 = *(const float4*)(Wp1 + 0);
    float4 w11 = *(const float4*)(Wp1 + 4);

#define STAGE(buf)                                                          \
    do {                                                                    \
        *(uint4*)&As[buf][r0][wc] = make_uint4(pk(a00.x, a00.y),            \
            pk(a00.z, a00.w), pk(a01.x, a01.y), pk(a01.z, a01.w));          \
        *(uint4*)&As[buf][r1][wc] = make_uint4(pk(a10.x, a10.y),            \
            pk(a10.z, a10.w), pk(a11.x, a11.y), pk(a11.z, a11.w));          \
        *(uint4*)&Bs[buf][r0][wc] = make_uint4(pk(w00.x, w00.y),            \
            pk(w00.z, w00.w), pk(w01.x, w01.y), pk(w01.z, w01.w));          \
        *(uint4*)&Bs[buf][r1][wc] = make_uint4(pk(w10.x, w10.y),            \
            pk(w10.z, w10.w), pk(w11.x, w11.y), pk(w11.z, w11.w));          \
    } while (0)

    STAGE(0);
    __syncthreads();

    int p = 0;
    for (int k0 = 0; k0 < K; k0 += BKT, p ^= 1) {
        const bool more = (k0 + BKT) < K;
        if (more) {
            const int ko = k0 + BKT;
            a00 = *(const float4*)(Ap0 + ko);
            a01 = *(const float4*)(Ap0 + ko + 4);
            a10 = *(const float4*)(Ap1 + ko);
            a11 = *(const float4*)(Ap1 + ko + 4);
            w00 = *(const float4*)(Wp0 + ko);
            w01 = *(const float4*)(Wp0 + ko + 4);
            w10 = *(const float4*)(Wp1 + ko);
            w11 = *(const float4*)(Wp1 + ko + 4);
        }

#pragma unroll
        for (int ks = 0; ks < 2; ks++) {
            const int kb = ks * 8;
            uint32_t af[4][4], bf[4][2];
#pragma unroll
            for (int im = 0; im < 4; im++) {
                const int r = wm + im * 16 + g;
                af[im][0] = As[p][r][kb + tg];
                af[im][1] = As[p][r + 8][kb + tg];
                af[im][2] = As[p][r][kb + tg + 4];
                af[im][3] = As[p][r + 8][kb + tg + 4];
            }
#pragma unroll
            for (int in = 0; in < 4; in++) {
                const int nr = wn + in * 8 + g;
                bf[in][0] = Bs[p][nr][kb + tg];
                bf[in][1] = Bs[p][nr][kb + tg + 4];
            }
#pragma unroll
            for (int im = 0; im < 4; im++)
#pragma unroll
                for (int in = 0; in < 4; in++)
                    mma_f16(acc[im][in], af[im], bf[in]);
        }

        if (more) STAGE(p ^ 1);
        __syncthreads();
    }
#undef STAGE

#pragma unroll
    for (int im = 0; im < 4; im++) {
        const int row = bm + wm + im * 16 + g;
#pragma unroll
        for (int in = 0; in < 4; in++) {
            const int col = bn + wn + in * 8 + 2 * tg;
            const float b0 = bias[col], b1 = bias[col + 1];
            float* Cr = C + (size_t)row * N + col;
            *(float2*)Cr = make_float2(acc[im][in][0] + b0,
                                       acc[im][in][1] + b1);
            float* Cr8 = C + (size_t)(row + 8) * N + col;
            *(float2*)Cr8 = make_float2(acc[im][in][2] + b0,
                                        acc[im][in][3] + b1);
        }
    }
}

// ---------------------------------------------------------------------------
// FP16 mma.sync attention, 1024 threads (32 warps, 50% occ).
// warp = (mt = warp>>3, oct = warp&7):
//   QK^T : octs 0-3 do 4 key-tiles, octs 4-7 do 3 (28 total); every oct also
//          does exactly 1 rel-table tile (8 total: Eh 4, Ew 4).
//   softmax: 2 rows per warp (khi/kwi inline; 64-reg budget).
//   PV   : 1 dim-tile (8 dims) per warp over 14 k16-chunks.
// Strides 36 / 116 / 228 as in R11 (verified conflict-free).
// ---------------------------------------------------------------------------
#define KP 224
#define QT 64
#define KWS 36
#define VWS 116
#define SSF 228
#define ES 32
#define NTH 1024

#define KS_OFF  0
#define QP_OFF  (KS_OFF + KP * KWS)
#define VT_OFF  (QP_OFF + QT * KWS)
#define SS_OFF  (VT_OFF + 64 * VWS)
#define PB_OFF  (SS_OFF + 64 * SSF)
#define RH_OFF  (PB_OFF + 64 * VWS)
#define RW_OFF  (RH_OFF + 32 * KWS)
#define EH_OFF  (RW_OFF + 32 * KWS)
#define EW_OFF  (EH_OFF + 64 * ES)
#define SIV_OFF (EW_OFF + 64 * ES)
#define ATT_SMEM_WORDS (SIV_OFF + 64)
#define ATT_SMEM_BYTES (ATT_SMEM_WORDS * 4)

__global__ __launch_bounds__(NTH, 1)
void attn_mma(const float* __restrict__ qkv,
              const float* __restrict__ rel_pos_h,
              const float* __restrict__ rel_pos_w,
              float* __restrict__ att_out) {
    extern __shared__ __align__(16) float sm[];
    uint32_t* Ksu = (uint32_t*)(sm + KS_OFF);
    uint32_t* Qpu = (uint32_t*)(sm + QP_OFF);
    uint32_t* Vtu = (uint32_t*)(sm + VT_OFF);
    float*    Ssm = sm + SS_OFF;
    uint32_t* Pbu = (uint32_t*)(sm + PB_OFF);
    __half*   Pbh = (__half*)Pbu;
    uint32_t* RHu = (uint32_t*)(sm + RH_OFF);
    uint32_t* RWu = (uint32_t*)(sm + RW_OFF);
    float*    Eh  = sm + EH_OFF;
    float*    Ew  = sm + EW_OFF;
    float*    Sinv = sm + SIV_OFF;

    const int bh = blockIdx.x;
    const int b = bh / NHEADS;
    const int head = bh % NHEADS;
    const int tid = threadIdx.x;
    const int warp = tid >> 5;
    const int lane = tid & 31;
    const int g = lane >> 2;
    const int tg = lane & 3;
    const int mt = warp >> 3;     // m-tile 0..3
    const int oct = warp & 7;     // octant 0..7

    const float* base = qkv + (size_t)b * TOK * NQKV + head * HD;

    // Stage K (half2 words, zero-padded) + rel tables (rows 27..31 zeroed)
    for (int i = tid; i < KP * 32; i += NTH) {
        const int t = i >> 5, d2 = i & 31;
        float2 v = make_float2(0.f, 0.f);
        if (t < TOK)
            v = *(const float2*)(base + (size_t)t * NQKV + HIDDEN + 2 * d2);
        Ksu[t * KWS + d2] = pk(v.x, v.y);
    }
    for (int i = tid; i < 32 * 32; i += NTH) {
        const int r = i >> 5, d2 = i & 31;
        float2 h = make_float2(0.f, 0.f), w = make_float2(0.f, 0.f);
        if (r < 27) {
            h = *(const float2*)(rel_pos_h + r * 64 + 2 * d2);
            w = *(const float2*)(rel_pos_w + r * 64 + 2 * d2);
        }
        RHu[r * KWS + d2] = pk(h.x, h.y);
        RWu[r * KWS + d2] = pk(w.x, w.y);
    }

    // Stage V^T via 56-token fp32 transpose chunks through the P buffer
    {
        float* Tmp = (float*)Pbu;  // 56*65 = 3640 floats <= 7424
        for (int c = 0; c < 4; c++) {
            const int t0 = c * 56;
            for (int i = tid; i < 56 * 64; i += NTH) {
                const int tt = i >> 6, d = i & 63;
                const int t = t0 + tt;
                Tmp[tt * 65 + d] =
                    (t < TOK) ? base[(size_t)t * NQKV + 2 * HIDDEN + d] : 0.f;
            }
            __syncthreads();
            for (int i = tid; i < 64 * 28; i += NTH) {
                const int d = i / 28, wt = i % 28;
                Vtu[d * VWS + c * 28 + wt] =
                    pk(Tmp[(2 * wt) * 65 + d], Tmp[(2 * wt + 1) * 65 + d]);
            }
            __syncthreads();
        }
    }

    const float scale = 0.125f;

    // Key-tile split: octs 0-3 -> 4 tiles, octs 4-7 -> 3 tiles (28 total)
    const int ntile = (oct < 4) ? 4 : 3;
    const int tbase = (oct < 4) ? oct * 4 : 16 + (oct - 4) * 3;
    // Rel tile: table by oct<4, column block by oct&3
    const uint32_t* Ru = (oct < 4) ? RHu : RWu;
    const int ecb = (oct & 3) * 8;

    for (int pass = 0; pass < 4; pass++) {
        const int q0 = pass * QT;

        for (int i = tid; i < QT * 32; i += NTH) {
            const int q = i >> 5, d2 = i & 31;
            const int qt = q0 + q;
            float2 v = make_float2(0.f, 0.f);
            if (qt < TOK)
                v = *(const float2*)(base + (size_t)qt * NQKV + 2 * d2);
            Qpu[q * KWS + d2] = pk(v.x, v.y);
        }
        __syncthreads();

        // QK^T (<=4 key-tiles/warp) + 1 rel-table tile/warp, shared af
        float s[4][4];
        float er[4];
#pragma unroll
        for (int j = 0; j < 4; j++)
#pragma unroll
            for (int q = 0; q < 4; q++) s[j][q] = 0.f;
#pragma unroll
        for (int q = 0; q < 4; q++) er[q] = 0.f;

#pragma unroll
        for (int ks = 0; ks < 4; ks++) {   // 64 dims = 4 x k16
            const int kb = ks * 8;
            uint32_t af[4];
            const int r = mt * 16 + g;
            af[0] = Qpu[r * KWS + kb + tg];
            af[1] = Qpu[(r + 8) * KWS + kb + tg];
            af[2] = Qpu[r * KWS + kb + tg + 4];
            af[3] = Qpu[(r + 8) * KWS + kb + tg + 4];
#pragma unroll
            for (int j = 0; j < 4; j++) {
                if (j < ntile) {
                    const int kn = (tbase + j) * 8;
                    uint32_t bf[2];
                    bf[0] = Ksu[(kn + g) * KWS + kb + tg];
                    bf[1] = Ksu[(kn + g) * KWS + kb + tg + 4];
                    mma_f16(s[j], af, bf);
                }
            }
            {
                const int rj = ecb + g;
                uint32_t bf[2];
                bf[0] = Ru[rj * KWS + kb + tg];
                bf[1] = Ru[rj * KWS + kb + tg + 4];
                mma_f16(er, af, bf);
            }
        }
#pragma unroll
        for (int j = 0; j < 4; j++) {
            if (j < ntile) {
                const int kn = (tbase + j) * 8;
                const int r = mt * 16 + g;
                *(float2*)&Ssm[r * SSF + kn + 2 * tg] =
                    make_float2(s[j][0], s[j][1]);
                *(float2*)&Ssm[(r + 8) * SSF + kn + 2 * tg] =
                    make_float2(s[j][2], s[j][3]);
            }
        }
        {
            float* Edst = (oct < 4) ? Eh : Ew;
            const int r = mt * 16 + g;
            const int col = ecb + 2 * tg;
            *(float2*)&Edst[r * ES + col] = make_float2(er[0], er[1]);
            *(float2*)&Edst[(r + 8) * ES + col] = make_float2(er[2], er[3]);
        }
        __syncthreads();

        // Softmax: 2 rows per warp; write P as halves
#pragma unroll
        for (int rr2 = 0; rr2 < 2; rr2++) {
            const int r = warp * 2 + rr2;
            const int qt = q0 + r;
            if (qt < TOK) {
                const int qh = qt / WIN, qw = qt - WIN * (qt / WIN);
                const float* EhR = Eh + r * ES;
                const float* EwR = Ew + r * ES;
                float sv[7];
                float m = -1e30f;
#pragma unroll
                for (int j = 0; j < 7; j++) {
                    const int k = lane + 32 * j;
                    if (k < TOK) {
                        const int kh = k / WIN;
                        const int kw = k - WIN * kh;
                        sv[j] = Ssm[r * SSF + k] * scale
                              + EhR[qh - kh + 13]
                              + EwR[qw - kw + 13];
                    } else sv[j] = -1e30f;
                    m = fmaxf(m, sv[j]);
                }
#pragma unroll
                for (int off = 16; off > 0; off >>= 1)
                    m = fmaxf(m, __shfl_xor_sync(0xffffffffu, m, off));
                float p[7], sum = 0.f;
#pragma unroll
                for (int j = 0; j < 7; j++) {
                    const int k = lane + 32 * j;
                    p[j] = (k < TOK) ? __expf(sv[j] - m) : 0.f;
                    sum += p[j];
                }
#pragma unroll
                for (int off = 16; off > 0; off >>= 1)
                    sum += __shfl_xor_sync(0xffffffffu, sum, off);
                if (lane == 0) Sinv[r] = 1.f / sum;
#pragma unroll
                for (int j = 0; j < 7; j++)
                    Pbh[r * (2 * VWS) + lane + 32 * j] = __float2half_rn(p[j]);
            }
        }
        __syncthreads();

        // PV: 1 dim-tile per warp over 14 k16-chunks (224 keys)
        float o[4];
#pragma unroll
        for (int q = 0; q < 4; q++) o[q] = 0.f;

#pragma unroll
        for (int ks = 0; ks < 14; ks++) {
            const int kb = ks * 8;
            uint32_t af[4];
            const int r = mt * 16 + g;
            af[0] = Pbu[r * VWS + kb + tg];
            af[1] = Pbu[(r + 8) * VWS + kb + tg];
            af[2] = Pbu[r * VWS + kb + tg + 4];
            af[3] = Pbu[(r + 8) * VWS + kb + tg + 4];
            const int nd = oct * 8 + g;
            uint32_t bf[2];
            bf[0] = Vtu[nd * VWS + kb + tg];
            bf[1] = Vtu[nd * VWS + kb + tg + 4];
            mma_f16(o, af, bf);
        }

        {
            const int qt0 = q0 + mt * 16 + g;
            const int qt1 = qt0 + 8;
            const float inv0 = (qt0 < TOK) ? Sinv[mt * 16 + g] : 0.f;
            const float inv1 = (qt1 < TOK) ? Sinv[mt * 16 + g + 8] : 0.f;
            const int d = oct * 8 + 2 * tg;
            if (qt0 < TOK) {
                float* o0 = att_out + (size_t)(b * TOK + qt0) * HIDDEN
                          + head * HD + d;
                *(float2*)o0 = make_float2(o[0] * inv0, o[1] * inv0);
            }
            if (qt1 < TOK) {
                float* o1 = att_out + (size_t)(b * TOK + qt1) * HIDDEN
                          + head * HD + d;
                *(float2*)o1 = make_float2(o[2] * inv1, o[3] * inv1);
            }
        }
        __syncthreads();
    }
}

// ---------------------------------------------------------------------------
extern "C" void kernel_launch(void* const* d_in, const int* in_sizes, int n_in,
                              void* d_out, int out_size) {
    const float* hidden = (const float*)d_in[0];
    const float* qkv_w  = (const float*)d_in[1];
    const float* qkv_b  = (const float*)d_in[2];
    const float* proj_w = (const float*)d_in[3];
    const float* proj_b = (const float*)d_in[4];
    const float* rel_h  = (const float*)d_in[5];
    const float* rel_w  = (const float*)d_in[6];
    float* out = (float*)d_out;

    void* p_qkv = nullptr;
    void* p_att = nullptr;
    cudaGetSymbolAddress(&p_qkv, g_qkv);
    cudaGetSymbolAddress(&p_att, g_att);

    cudaFuncSetAttribute(attn_mma,
                         cudaFuncAttributeMaxDynamicSharedMemorySize,
                         ATT_SMEM_BYTES);

    // 1) QKV projection (fp16 tensor cores, fp32 accumulate)
    gemm_f16<<<dim3(NQKV / 128, MTOK / 128), 256>>>(
        hidden, qkv_w, qkv_b, (float*)p_qkv, NQKV, HIDDEN);

    // 2) Attention (fp16 mma.sync, 32 warps/block, fp32 softmax/accumulate)
    attn_mma<<<BATCH * NHEADS, NTH, ATT_SMEM_BYTES>>>(
        (const float*)p_qkv, rel_h, rel_w, (float*)p_att);

    // 3) Output projection (fp16 tensor cores, fp32 accumulate)
    gemm_f16<<<dim3(HIDDEN / 128, MTOK / 128), 256>>>(
        (const float*)p_att, proj_w, proj_b, out, HIDDEN, HIDDEN);
}

// round 15
// speedup vs baseline: 1.7201x; 1.0984x over previous
#include <cuda_runtime.h>
#include <cuda_fp16.h>
#include <math.h>
#include <stdint.h>

#define HIDDEN 768
#define NHEADS 12
#define HD 64
#define WIN 14
#define TOK 196                 // WIN*WIN
#define BATCH 256
#define MTOK (BATCH * TOK)      // 50176
#define NQKV (3 * HIDDEN)       // 2304

// Scratch (allocation-free rule: __device__ globals) — fp16 intermediates
__device__ __half g_qkvh[(size_t)MTOK * NQKV];    // 50176 x 2304 (half)
__device__ __half g_atth[(size_t)MTOK * HIDDEN];  // 50176 x 768 (half)

__device__ __forceinline__ uint32_t pk(float x, float y) {
    __half2 h = __floats2half2_rn(x, y);
    return *reinterpret_cast<uint32_t*>(&h);
}

__device__ __forceinline__ void mma_f16(float c[4], const uint32_t a[4],
                                        const uint32_t b[2]) {
    asm("mma.sync.aligned.m16n8k16.row.col.f32.f16.f16.f32 "
        "{%0,%1,%2,%3}, {%4,%5,%6,%7}, {%8,%9}, {%0,%1,%2,%3};"
        : "+f"(c[0]), "+f"(c[1]), "+f"(c[2]), "+f"(c[3])
        : "r"(a[0]), "r"(a[1]), "r"(a[2]), "r"(a[3]), "r"(b[0]), "r"(b[1]));
}

// ---------------------------------------------------------------------------
// FP16 tensor-core GEMM (fp32 accumulate):  C = A[M,K] @ W[N,K]^T + bias
// BM=BN=128, BK=32 (16 half2 words/row, stride 20 -> conflict-free).
// 256 threads, 8 warps, warp tile 64x32. Double-buffered smem.
// A_HALF: A is __half in gmem (raw uint4 staging, no cvt).
// C_HALF: C written as __half (half STG bytes).
// ---------------------------------------------------------------------------
#define BKT 32
#define SW 20    // smem row stride in half2 words

template <bool A_HALF, bool C_HALF>
__global__ __launch_bounds__(256, 2)
void gemm_f16t(const void* __restrict__ Av, const float* __restrict__ W,
               const float* __restrict__ bias, void* __restrict__ Cv,
               int N, int K) {
    __shared__ uint32_t As[2][128][SW];
    __shared__ uint32_t Bs[2][128][SW];

    const int bm = blockIdx.y * 128;
    const int bn = blockIdx.x * 128;
    const int tid = threadIdx.x;
    const int warp = tid >> 5;
    const int lane = tid & 31;
    const int g = lane >> 2;
    const int tg = lane & 3;
    const int wm = (warp >> 2) * 64;
    const int wn = (warp & 3) * 32;

    const int r0 = tid >> 2;
    const int r1 = r0 + 64;
    const int fc = (tid & 3) * 8;   // k-offset (elements)
    const int wc = (tid & 3) * 4;   // word col

    float acc[4][4][4];
#pragma unroll
    for (int im = 0; im < 4; im++)
#pragma unroll
        for (int in = 0; in < 4; in++)
#pragma unroll
            for (int q = 0; q < 4; q++) acc[im][in][q] = 0.f;

    const float*  Af = (const float*)Av;
    const __half* Ah = (const __half*)Av;

    const float* Wp0 = W + (size_t)(bn + r0) * K + fc;
    const float* Wp1 = W + (size_t)(bn + r1) * K + fc;

    float4 a00, a01, a10, a11;
    uint4 ha0, ha1;
    if constexpr (A_HALF) {
        ha0 = *(const uint4*)(Ah + (size_t)(bm + r0) * K + fc);
        ha1 = *(const uint4*)(Ah + (size_t)(bm + r1) * K + fc);
    } else {
        const float* Ap0 = Af + (size_t)(bm + r0) * K + fc;
        const float* Ap1 = Af + (size_t)(bm + r1) * K + fc;
        a00 = *(const float4*)(Ap0 + 0);
        a01 = *(const float4*)(Ap0 + 4);
        a10 = *(const float4*)(Ap1 + 0);
        a11 = *(const float4*)(Ap1 + 4);
    }
    float4 w00 = *(const float4*)(Wp0 + 0);
    float4 w01 = *(const float4*)(Wp0 + 4);
    float4 w10 = *(const float4*)(Wp1 + 0);
    float4 w11 = *(const float4*)(Wp1 + 4);

#define STAGE(buf)                                                          \
    do {                                                                    \
        if constexpr (A_HALF) {                                             \
            *(uint4*)&As[buf][r0][wc] = ha0;                                \
            *(uint4*)&As[buf][r1][wc] = ha1;                                \
        } else {                                                            \
            *(uint4*)&As[buf][r0][wc] = make_uint4(pk(a00.x, a00.y),        \
                pk(a00.z, a00.w), pk(a01.x, a01.y), pk(a01.z, a01.w));      \
            *(uint4*)&As[buf][r1][wc] = make_uint4(pk(a10.x, a10.y),        \
                pk(a10.z, a10.w), pk(a11.x, a11.y), pk(a11.z, a11.w));      \
        }                                                                   \
        *(uint4*)&Bs[buf][r0][wc] = make_uint4(pk(w00.x, w00.y),            \
            pk(w00.z, w00.w), pk(w01.x, w01.y), pk(w01.z, w01.w));          \
        *(uint4*)&Bs[buf][r1][wc] = make_uint4(pk(w10.x, w10.y),            \
            pk(w10.z, w10.w), pk(w11.x, w11.y), pk(w11.z, w11.w));          \
    } while (0)

    STAGE(0);
    __syncthreads();

    int p = 0;
    for (int k0 = 0; k0 < K; k0 += BKT, p ^= 1) {
        const bool more = (k0 + BKT) < K;
        if (more) {
            const int ko = k0 + BKT;
            if constexpr (A_HALF) {
                ha0 = *(const uint4*)(Ah + (size_t)(bm + r0) * K + fc + ko);
                ha1 = *(const uint4*)(Ah + (size_t)(bm + r1) * K + fc + ko);
            } else {
                const float* Ap0 = Af + (size_t)(bm + r0) * K + fc + ko;
                const float* Ap1 = Af + (size_t)(bm + r1) * K + fc + ko;
                a00 = *(const float4*)(Ap0 + 0);
                a01 = *(const float4*)(Ap0 + 4);
                a10 = *(const float4*)(Ap1 + 0);
                a11 = *(const float4*)(Ap1 + 4);
            }
            w00 = *(const float4*)(Wp0 + ko);
            w01 = *(const float4*)(Wp0 + ko + 4);
            w10 = *(const float4*)(Wp1 + ko);
            w11 = *(const float4*)(Wp1 + ko + 4);
        }

#pragma unroll
        for (int ks = 0; ks < 2; ks++) {
            const int kb = ks * 8;
            uint32_t af[4][4], bf[4][2];
#pragma unroll
            for (int im = 0; im < 4; im++) {
                const int r = wm + im * 16 + g;
                af[im][0] = As[p][r][kb + tg];
                af[im][1] = As[p][r + 8][kb + tg];
                af[im][2] = As[p][r][kb + tg + 4];
                af[im][3] = As[p][r + 8][kb + tg + 4];
            }
#pragma unroll
            for (int in = 0; in < 4; in++) {
                const int nr = wn + in * 8 + g;
                bf[in][0] = Bs[p][nr][kb + tg];
                bf[in][1] = Bs[p][nr][kb + tg + 4];
            }
#pragma unroll
            for (int im = 0; im < 4; im++)
#pragma unroll
                for (int in = 0; in < 4; in++)
                    mma_f16(acc[im][in], af[im], bf[in]);
        }

        if (more) STAGE(p ^ 1);
        __syncthreads();
    }
#undef STAGE

#pragma unroll
    for (int im = 0; im < 4; im++) {
        const int row = bm + wm + im * 16 + g;
#pragma unroll
        for (int in = 0; in < 4; in++) {
            const int col = bn + wn + in * 8 + 2 * tg;
            const float b0 = bias[col], b1 = bias[col + 1];
            if constexpr (C_HALF) {
                __half* Cr = (__half*)Cv + (size_t)row * N + col;
                *(uint32_t*)Cr = pk(acc[im][in][0] + b0, acc[im][in][1] + b1);
                __half* Cr8 = (__half*)Cv + (size_t)(row + 8) * N + col;
                *(uint32_t*)Cr8 = pk(acc[im][in][2] + b0, acc[im][in][3] + b1);
            } else {
                float* Cr = (float*)Cv + (size_t)row * N + col;
                *(float2*)Cr = make_float2(acc[im][in][0] + b0,
                                           acc[im][in][1] + b1);
                float* Cr8 = (float*)Cv + (size_t)(row + 8) * N + col;
                *(float2*)Cr8 = make_float2(acc[im][in][2] + b0,
                                            acc[im][in][3] + b1);
            }
        }
    }
}

// ---------------------------------------------------------------------------
// FP16 mma.sync attention, 1024 threads (32 warps). QKV input is __half:
// K/Q staging = raw word copies (no cvt); V transpose moves half data.
// Output written as __half (proj consumes fp16 anyway -> no extra rounding).
// ---------------------------------------------------------------------------
#define KP 224
#define QT 64
#define KWS 36
#define VWS 116
#define SSF 228
#define ES 32
#define NTH 1024

#define KS_OFF  0
#define QP_OFF  (KS_OFF + KP * KWS)
#define VT_OFF  (QP_OFF + QT * KWS)
#define SS_OFF  (VT_OFF + 64 * VWS)
#define PB_OFF  (SS_OFF + 64 * SSF)
#define RH_OFF  (PB_OFF + 64 * VWS)
#define RW_OFF  (RH_OFF + 32 * KWS)
#define EH_OFF  (RW_OFF + 32 * KWS)
#define EW_OFF  (EH_OFF + 64 * ES)
#define SIV_OFF (EW_OFF + 64 * ES)
#define ATT_SMEM_WORDS (SIV_OFF + 64)
#define ATT_SMEM_BYTES (ATT_SMEM_WORDS * 4)

__global__ __launch_bounds__(NTH, 1)
void attn_mma(const __half* __restrict__ qkv,
              const float* __restrict__ rel_pos_h,
              const float* __restrict__ rel_pos_w,
              __half* __restrict__ att_out) {
    extern __shared__ __align__(16) float sm[];
    uint32_t* Ksu = (uint32_t*)(sm + KS_OFF);
    uint32_t* Qpu = (uint32_t*)(sm + QP_OFF);
    uint32_t* Vtu = (uint32_t*)(sm + VT_OFF);
    float*    Ssm = sm + SS_OFF;
    uint32_t* Pbu = (uint32_t*)(sm + PB_OFF);
    __half*   Pbh = (__half*)Pbu;
    uint32_t* RHu = (uint32_t*)(sm + RH_OFF);
    uint32_t* RWu = (uint32_t*)(sm + RW_OFF);
    float*    Eh  = sm + EH_OFF;
    float*    Ew  = sm + EW_OFF;
    float*    Sinv = sm + SIV_OFF;

    const int bh = blockIdx.x;
    const int b = bh / NHEADS;
    const int head = bh % NHEADS;
    const int tid = threadIdx.x;
    const int warp = tid >> 5;
    const int lane = tid & 31;
    const int g = lane >> 2;
    const int tg = lane & 3;
    const int mt = warp >> 3;     // m-tile 0..3
    const int oct = warp & 7;     // octant 0..7

    const __half* base = qkv + (size_t)b * TOK * NQKV + head * HD;

    // Stage K: raw half2-word copies (no conversion)
    for (int i = tid; i < KP * 32; i += NTH) {
        const int t = i >> 5, d2 = i & 31;
        uint32_t w = 0;
        if (t < TOK)
            w = ((const uint32_t*)(base + (size_t)t * NQKV + HIDDEN))[d2];
        Ksu[t * KWS + d2] = w;
    }
    // Rel tables (fp32 gmem -> half2 words; rows 27..31 zeroed)
    for (int i = tid; i < 32 * 32; i += NTH) {
        const int r = i >> 5, d2 = i & 31;
        float2 h = make_float2(0.f, 0.f), w = make_float2(0.f, 0.f);
        if (r < 27) {
            h = *(const float2*)(rel_pos_h + r * 64 + 2 * d2);
            w = *(const float2*)(rel_pos_w + r * 64 + 2 * d2);
        }
        RHu[r * KWS + d2] = pk(h.x, h.y);
        RWu[r * KWS + d2] = pk(w.x, w.y);
    }

    // Stage V^T: 56-token chunks, half data bounced through the P buffer.
    // Word writes at stride 33 (conflict-free); half-granular repack reads.
    {
        uint32_t* TmpW = Pbu;            // 56*33 words = 1848 <= 7424
        __half*   TmpH = (__half*)Pbu;   // stride 66 halves per row
        for (int c = 0; c < 4; c++) {
            const int t0 = c * 56;
            for (int i = tid; i < 56 * 32; i += NTH) {
                const int tt = i >> 5, d2 = i & 31;
                const int t = t0 + tt;
                uint32_t w = 0;
                if (t < TOK)
                    w = ((const uint32_t*)(base + (size_t)t * NQKV +
                                           2 * HIDDEN))[d2];
                TmpW[tt * 33 + d2] = w;
            }
            __syncthreads();
            for (int i = tid; i < 64 * 28; i += NTH) {
                const int d = i / 28, wt = i % 28;
                __half2 h2 = __halves2half2(TmpH[(2 * wt) * 66 + d],
                                            TmpH[(2 * wt + 1) * 66 + d]);
                Vtu[d * VWS + c * 28 + wt] = *(uint32_t*)&h2;
            }
            __syncthreads();
        }
    }

    const float scale = 0.125f;

    // Key-tile split: octs 0-3 -> 4 tiles, octs 4-7 -> 3 tiles (28 total)
    const int ntile = (oct < 4) ? 4 : 3;
    const int tbase = (oct < 4) ? oct * 4 : 16 + (oct - 4) * 3;
    const uint32_t* Ru = (oct < 4) ? RHu : RWu;
    const int ecb = (oct & 3) * 8;

    for (int pass = 0; pass < 4; pass++) {
        const int q0 = pass * QT;

        for (int i = tid; i < QT * 32; i += NTH) {
            const int q = i >> 5, d2 = i & 31;
            const int qt = q0 + q;
            uint32_t w = 0;
            if (qt < TOK)
                w = ((const uint32_t*)(base + (size_t)qt * NQKV))[d2];
            Qpu[q * KWS + d2] = w;
        }
        __syncthreads();

        // QK^T (<=4 key-tiles/warp) + 1 rel-table tile/warp, shared af
        float s[4][4];
        float er[4];
#pragma unroll
        for (int j = 0; j < 4; j++)
#pragma unroll
            for (int q = 0; q < 4; q++) s[j][q] = 0.f;
#pragma unroll
        for (int q = 0; q < 4; q++) er[q] = 0.f;

#pragma unroll
        for (int ks = 0; ks < 4; ks++) {   // 64 dims = 4 x k16
            const int kb = ks * 8;
            uint32_t af[4];
            const int r = mt * 16 + g;
            af[0] = Qpu[r * KWS + kb + tg];
            af[1] = Qpu[(r + 8) * KWS + kb + tg];
            af[2] = Qpu[r * KWS + kb + tg + 4];
            af[3] = Qpu[(r + 8) * KWS + kb + tg + 4];
#pragma unroll
            for (int j = 0; j < 4; j++) {
                if (j < ntile) {
                    const int kn = (tbase + j) * 8;
                    uint32_t bf[2];
                    bf[0] = Ksu[(kn + g) * KWS + kb + tg];
                    bf[1] = Ksu[(kn + g) * KWS + kb + tg + 4];
                    mma_f16(s[j], af, bf);
                }
            }
            {
                const int rj = ecb + g;
                uint32_t bf[2];
                bf[0] = Ru[rj * KWS + kb + tg];
                bf[1] = Ru[rj * KWS + kb + tg + 4];
                mma_f16(er, af, bf);
            }
        }
#pragma unroll
        for (int j = 0; j < 4; j++) {
            if (j < ntile) {
                const int kn = (tbase + j) * 8;
                const int r = mt * 16 + g;
                *(float2*)&Ssm[r * SSF + kn + 2 * tg] =
                    make_float2(s[j][0], s[j][1]);
                *(float2*)&Ssm[(r + 8) * SSF + kn + 2 * tg] =
                    make_float2(s[j][2], s[j][3]);
            }
        }
        {
            float* Edst = (oct < 4) ? Eh : Ew;
            const int r = mt * 16 + g;
            const int col = ecb + 2 * tg;
            *(float2*)&Edst[r * ES + col] = make_float2(er[0], er[1]);
            *(float2*)&Edst[(r + 8) * ES + col] = make_float2(er[2], er[3]);
        }
        __syncthreads();

        // Softmax: 2 rows per warp; write P as halves
#pragma unroll
        for (int rr2 = 0; rr2 < 2; rr2++) {
            const int r = warp * 2 + rr2;
            const int qt = q0 + r;
            if (qt < TOK) {
                const int qh = qt / WIN, qw = qt - WIN * (qt / WIN);
                const float* EhR = Eh + r * ES;
                const float* EwR = Ew + r * ES;
                float sv[7];
                float m = -1e30f;
#pragma unroll
                for (int j = 0; j < 7; j++) {
                    const int k = lane + 32 * j;
                    if (k < TOK) {
                        const int kh = k / WIN;
                        const int kw = k - WIN * kh;
                        sv[j] = Ssm[r * SSF + k] * scale
                              + EhR[qh - kh + 13]
                              + EwR[qw - kw + 13];
                    } else sv[j] = -1e30f;
                    m = fmaxf(m, sv[j]);
                }
#pragma unroll
                for (int off = 16; off > 0; off >>= 1)
                    m = fmaxf(m, __shfl_xor_sync(0xffffffffu, m, off));
                float p[7], sum = 0.f;
#pragma unroll
                for (int j = 0; j < 7; j++) {
                    const int k = lane + 32 * j;
                    p[j] = (k < TOK) ? __expf(sv[j] - m) : 0.f;
                    sum += p[j];
                }
#pragma unroll
                for (int off = 16; off > 0; off >>= 1)
                    sum += __shfl_xor_sync(0xffffffffu, sum, off);
                if (lane == 0) Sinv[r] = 1.f / sum;
#pragma unroll
                for (int j = 0; j < 7; j++)
                    Pbh[r * (2 * VWS) + lane + 32 * j] = __float2half_rn(p[j]);
            }
        }
        __syncthreads();

        // PV: 1 dim-tile per warp over 14 k16-chunks (224 keys)
        float o[4];
#pragma unroll
        for (int q = 0; q < 4; q++) o[q] = 0.f;

#pragma unroll
        for (int ks = 0; ks < 14; ks++) {
            const int kb = ks * 8;
            uint32_t af[4];
            const int r = mt * 16 + g;
            af[0] = Pbu[r * VWS + kb + tg];
            af[1] = Pbu[(r + 8) * VWS + kb + tg];
            af[2] = Pbu[r * VWS + kb + tg + 4];
            af[3] = Pbu[(r + 8) * VWS + kb + tg + 4];
            const int nd = oct * 8 + g;
            uint32_t bf[2];
            bf[0] = Vtu[nd * VWS + kb + tg];
            bf[1] = Vtu[nd * VWS + kb + tg + 4];
            mma_f16(o, af, bf);
        }

        {
            const int qt0 = q0 + mt * 16 + g;
            const int qt1 = qt0 + 8;
            const float inv0 = (qt0 < TOK) ? Sinv[mt * 16 + g] : 0.f;
            const float inv1 = (qt1 < TOK) ? Sinv[mt * 16 + g + 8] : 0.f;
            const int d = oct * 8 + 2 * tg;
            if (qt0 < TOK) {
                __half* o0 = att_out + (size_t)(b * TOK + qt0) * HIDDEN
                           + head * HD + d;
                *(uint32_t*)o0 = pk(o[0] * inv0, o[1] * inv0);
            }
            if (qt1 < TOK) {
                __half* o1 = att_out + (size_t)(b * TOK + qt1) * HIDDEN
                           + head * HD + d;
                *(uint32_t*)o1 = pk(o[2] * inv1, o[3] * inv1);
            }
        }
        __syncthreads();
    }
}

// ---------------------------------------------------------------------------
extern "C" void kernel_launch(void* const* d_in, const int* in_sizes, int n_in,
                              void* d_out, int out_size) {
    const float* hidden = (const float*)d_in[0];
    const float* qkv_w  = (const float*)d_in[1];
    const float* qkv_b  = (const float*)d_in[2];
    const float* proj_w = (const float*)d_in[3];
    const float* proj_b = (const float*)d_in[4];
    const float* rel_h  = (const float*)d_in[5];
    const float* rel_w  = (const float*)d_in[6];
    float* out = (float*)d_out;

    void* p_qkv = nullptr;
    void* p_att = nullptr;
    cudaGetSymbolAddress(&p_qkv, g_qkvh);
    cudaGetSymbolAddress(&p_att, g_atth);

    cudaFuncSetAttribute(attn_mma,
                         cudaFuncAttributeMaxDynamicSharedMemorySize,
                         ATT_SMEM_BYTES);

    // 1) QKV projection: fp32 A -> fp16 out
    gemm_f16t<false, true><<<dim3(NQKV / 128, MTOK / 128), 256>>>(
        hidden, qkv_w, qkv_b, p_qkv, NQKV, HIDDEN);

    // 2) Attention (fp16 in/out, fp32 softmax/accumulate)
    attn_mma<<<BATCH * NHEADS, NTH, ATT_SMEM_BYTES>>>(
        (const __half*)p_qkv, rel_h, rel_w, (__half*)p_att);

    // 3) Output projection: fp16 A -> fp32 out
    gemm_f16t<true, false><<<dim3(HIDDEN / 128, MTOK / 128), 256>>>(
        p_att, proj_w, proj_b, out, HIDDEN, HIDDEN);
}

// round 17
// speedup vs baseline: 2.2952x; 1.3344x over previous
#include <cuda_runtime.h>
#include <cuda_fp16.h>
#include <math.h>
#include <stdint.h>

#define HIDDEN 768
#define NHEADS 12
#define HD 64
#define WIN 14
#define TOK 196                 // WIN*WIN
#define BATCH 256
#define MTOK (BATCH * TOK)      // 50176
#define NQKV (3 * HIDDEN)       // 2304

// Scratch (allocation-free rule: __device__ globals) — fp16 everywhere
__device__ __half g_qkvh[(size_t)MTOK * NQKV];     // 50176 x 2304
__device__ __half g_atth[(size_t)MTOK * HIDDEN];   // 50176 x 768
__device__ __half g_hidh[(size_t)MTOK * HIDDEN];   // hidden in fp16
__device__ __half g_wqkvh[(size_t)NQKV * HIDDEN];  // qkv_w in fp16
__device__ __half g_wprjh[(size_t)HIDDEN * HIDDEN];// proj_w in fp16

__device__ __forceinline__ uint32_t pk(float x, float y) {
    __half2 h = __floats2half2_rn(x, y);
    return *reinterpret_cast<uint32_t*>(&h);
}

__device__ __forceinline__ uint32_t smem_u32(const void* p) {
    uint32_t a;
    asm("{ .reg .u64 t; cvta.to.shared.u64 t, %1; cvt.u32.u64 %0, t; }"
        : "=r"(a) : "l"(p));
    return a;
}

__device__ __forceinline__ void mma_f16(float c[4], const uint32_t a[4],
                                        const uint32_t b[2]) {
    asm("mma.sync.aligned.m16n8k16.row.col.f32.f16.f16.f32 "
        "{%0,%1,%2,%3}, {%4,%5,%6,%7}, {%8,%9}, {%0,%1,%2,%3};"
        : "+f"(c[0]), "+f"(c[1]), "+f"(c[2]), "+f"(c[3])
        : "r"(a[0]), "r"(a[1]), "r"(a[2]), "r"(a[3]), "r"(b[0]), "r"(b[1]));
}

__device__ __forceinline__ void ldsm_x2_t(uint32_t& r0, uint32_t& r1,
                                          uint32_t addr) {
    asm volatile(
        "ldmatrix.sync.aligned.m8n8.x2.trans.shared.b16 {%0,%1}, [%2];"
        : "=r"(r0), "=r"(r1) : "r"(addr));
}

// ---------------------------------------------------------------------------
// fp32 -> fp16 convert (n % 8 == 0), identical rounding to the old staging
// ---------------------------------------------------------------------------
__global__ void f2h(const float* __restrict__ s, __half* __restrict__ d,
                    int n) {
    const int i = (blockIdx.x * blockDim.x + threadIdx.x) * 8;
    if (i < n) {
        const float4 a = *(const float4*)(s + i);
        const float4 b = *(const float4*)(s + i + 4);
        *(uint4*)(d + i) = make_uint4(pk(a.x, a.y), pk(a.z, a.w),
                                      pk(b.x, b.y), pk(b.z, b.w));
    }
}

// ---------------------------------------------------------------------------
// All-fp16 tensor-core GEMM (fp32 accumulate):  C = A[M,K] @ W[N,K]^T + bias
// BM=BN=128, BK=32, 256 threads, warp tile 64x32. Raw uint4 staging for both
// operands (no cvt in the mainloop). Double-buffered smem.
// ---------------------------------------------------------------------------
#define BKT 32
#define SW 20    // smem row stride in half2 words

template <bool C_HALF>
__global__ __launch_bounds__(256, 2)
void gemm_hh(const __half* __restrict__ A, const __half* __restrict__ W,
             const float* __restrict__ bias, void* __restrict__ Cv,
             int N, int K) {
    __shared__ uint32_t As[2][128][SW];
    __shared__ uint32_t Bs[2][128][SW];

    const int bm = blockIdx.y * 128;
    const int bn = blockIdx.x * 128;
    const int tid = threadIdx.x;
    const int warp = tid >> 5;
    const int lane = tid & 31;
    const int g = lane >> 2;
    const int tg = lane & 3;
    const int wm = (warp >> 2) * 64;
    const int wn = (warp & 3) * 32;

    const int r0 = tid >> 2;
    const int r1 = r0 + 64;
    const int fc = (tid & 3) * 8;   // element (half) offset
    const int wc = (tid & 3) * 4;   // word col

    float acc[4][4][4];
#pragma unroll
    for (int im = 0; im < 4; im++)
#pragma unroll
        for (int in = 0; in < 4; in++)
#pragma unroll
            for (int q = 0; q < 4; q++) acc[im][in][q] = 0.f;

    const __half* Ap0 = A + (size_t)(bm + r0) * K + fc;
    const __half* Ap1 = A + (size_t)(bm + r1) * K + fc;
    const __half* Wp0 = W + (size_t)(bn + r0) * K + fc;
    const __half* Wp1 = W + (size_t)(bn + r1) * K + fc;

    uint4 ha0 = *(const uint4*)Ap0;
    uint4 ha1 = *(const uint4*)Ap1;
    uint4 hw0 = *(const uint4*)Wp0;
    uint4 hw1 = *(const uint4*)Wp1;

    *(uint4*)&As[0][r0][wc] = ha0;
    *(uint4*)&As[0][r1][wc] = ha1;
    *(uint4*)&Bs[0][r0][wc] = hw0;
    *(uint4*)&Bs[0][r1][wc] = hw1;
    __syncthreads();

    int p = 0;
    for (int k0 = 0; k0 < K; k0 += BKT, p ^= 1) {
        const bool more = (k0 + BKT) < K;
        if (more) {
            const int ko = k0 + BKT;
            ha0 = *(const uint4*)(Ap0 + ko);
            ha1 = *(const uint4*)(Ap1 + ko);
            hw0 = *(const uint4*)(Wp0 + ko);
            hw1 = *(const uint4*)(Wp1 + ko);
        }

#pragma unroll
        for (int ks = 0; ks < 2; ks++) {
            const int kb = ks * 8;
            uint32_t af[4][4], bf[4][2];
#pragma unroll
            for (int im = 0; im < 4; im++) {
                const int r = wm + im * 16 + g;
                af[im][0] = As[p][r][kb + tg];
                af[im][1] = As[p][r + 8][kb + tg];
                af[im][2] = As[p][r][kb + tg + 4];
                af[im][3] = As[p][r + 8][kb + tg + 4];
            }
#pragma unroll
            for (int in = 0; in < 4; in++) {
                const int nr = wn + in * 8 + g;
                bf[in][0] = Bs[p][nr][kb + tg];
                bf[in][1] = Bs[p][nr][kb + tg + 4];
            }
#pragma unroll
            for (int im = 0; im < 4; im++)
#pragma unroll
                for (int in = 0; in < 4; in++)
                    mma_f16(acc[im][in], af[im], bf[in]);
        }

        if (more) {
            *(uint4*)&As[p ^ 1][r0][wc] = ha0;
            *(uint4*)&As[p ^ 1][r1][wc] = ha1;
            *(uint4*)&Bs[p ^ 1][r0][wc] = hw0;
            *(uint4*)&Bs[p ^ 1][r1][wc] = hw1;
        }
        __syncthreads();
    }

#pragma unroll
    for (int im = 0; im < 4; im++) {
        const int row = bm + wm + im * 16 + g;
#pragma unroll
        for (int in = 0; in < 4; in++) {
            const int col = bn + wn + in * 8 + 2 * tg;
            const float b0 = bias[col], b1 = bias[col + 1];
            if constexpr (C_HALF) {
                __half* Cr = (__half*)Cv + (size_t)row * N + col;
                *(uint32_t*)Cr = pk(acc[im][in][0] + b0, acc[im][in][1] + b1);
                __half* Cr8 = (__half*)Cv + (size_t)(row + 8) * N + col;
                *(uint32_t*)Cr8 = pk(acc[im][in][2] + b0, acc[im][in][3] + b1);
            } else {
                float* Cr = (float*)Cv + (size_t)row * N + col;
                *(float2*)Cr = make_float2(acc[im][in][0] + b0,
                                           acc[im][in][1] + b1);
                float* Cr8 = (float*)Cv + (size_t)(row + 8) * N + col;
                *(float2*)Cr8 = make_float2(acc[im][in][2] + b0,
                                            acc[im][in][3] + b1);
            }
        }
    }
}

// ---------------------------------------------------------------------------
// FP16 mma.sync attention, 1024 threads (32 warps).
//  - K, V, Q(all 256 padded rows), rel tables staged ONCE (raw word copies);
//    one block-wide __syncthreads total.
//  - V kept row-major; PV B-fragments loaded via ldmatrix.x2.trans
//    (transpose in the LDSM unit -> no smem transpose phase).
//  - Intra-pass sync via named barriers per m-tile group (8 warps / 256 thr):
//    the 4 groups pipeline independently; 2 barriers per pass.
// ---------------------------------------------------------------------------
#define KP 224
#define QT 64
#define KWS 36    // K/V/Q/R word stride (36 % 32 = 4 -> conflict-free)
#define VWS 116   // P word stride
#define SSF 228   // score fp32 stride
#define ES 32
#define NTH 1024

#define KS_OFF  0                          // 224*36 = 8064
#define VS_OFF  (KS_OFF + KP * KWS)        // 224*36 = 8064
#define QP_OFF  (VS_OFF + KP * KWS)        // 256*36 = 9216
#define SS_OFF  (QP_OFF + 256 * KWS)       // 64*228 = 14592 (fp32)
#define PB_OFF  (SS_OFF + 64 * SSF)        // 64*116 = 7424
#define RH_OFF  (PB_OFF + 64 * VWS)        // 32*36
#define RW_OFF  (RH_OFF + 32 * KWS)
#define EH_OFF  (RW_OFF + 32 * KWS)        // 64*32 fp32
#define EW_OFF  (EH_OFF + 64 * ES)
#define SIV_OFF (EW_OFF + 64 * ES)
#define ATT_SMEM_WORDS (SIV_OFF + 64)
#define ATT_SMEM_BYTES (ATT_SMEM_WORDS * 4)

__global__ __launch_bounds__(NTH, 1)
void attn_mma(const __half* __restrict__ qkv,
              const float* __restrict__ rel_pos_h,
              const float* __restrict__ rel_pos_w,
              __half* __restrict__ att_out) {
    extern __shared__ __align__(16) float sm[];
    uint32_t* Ksu = (uint32_t*)(sm + KS_OFF);
    uint32_t* Vsu = (uint32_t*)(sm + VS_OFF);
    uint32_t* Qpu = (uint32_t*)(sm + QP_OFF);
    float*    Ssm = sm + SS_OFF;
    uint32_t* Pbu = (uint32_t*)(sm + PB_OFF);
    __half*   Pbh = (__half*)Pbu;
    uint32_t* RHu = (uint32_t*)(sm + RH_OFF);
    uint32_t* RWu = (uint32_t*)(sm + RW_OFF);
    float*    Eh  = sm + EH_OFF;
    float*    Ew  = sm + EW_OFF;
    float*    Sinv = sm + SIV_OFF;

    const int bh = blockIdx.x;
    const int b = bh / NHEADS;
    const int head = bh % NHEADS;
    const int tid = threadIdx.x;
    const int warp = tid >> 5;
    const int lane = tid & 31;
    const int g = lane >> 2;
    const int tg = lane & 3;
    const int mt = warp >> 3;     // m-tile group 0..3
    const int oct = warp & 7;     // octant 0..7

    const __half* base = qkv + (size_t)b * TOK * NQKV + head * HD;

    // ---- stage K and V (raw word copies, zero-padded rows) ----
    for (int i = tid; i < KP * 32; i += NTH) {
        const int t = i >> 5, d2 = i & 31;
        uint32_t wk = 0, wv = 0;
        if (t < TOK) {
            wk = ((const uint32_t*)(base + (size_t)t * NQKV + HIDDEN))[d2];
            wv = ((const uint32_t*)(base + (size_t)t * NQKV + 2 * HIDDEN))[d2];
        }
        Ksu[t * KWS + d2] = wk;
        Vsu[t * KWS + d2] = wv;
    }
    // ---- stage ALL Q rows (padded to 256) ----
    for (int i = tid; i < 256 * 32; i += NTH) {
        const int t = i >> 5, d2 = i & 31;
        uint32_t w = 0;
        if (t < TOK)
            w = ((const uint32_t*)(base + (size_t)t * NQKV))[d2];
        Qpu[t * KWS + d2] = w;
    }
    // ---- rel tables (rows 27..31 zeroed) ----
    for (int i = tid; i < 32 * 32; i += NTH) {
        const int r = i >> 5, d2 = i & 31;
        float2 h = make_float2(0.f, 0.f), w = make_float2(0.f, 0.f);
        if (r < 27) {
            h = *(const float2*)(rel_pos_h + r * 64 + 2 * d2);
            w = *(const float2*)(rel_pos_w + r * 64 + 2 * d2);
        }
        RHu[r * KWS + d2] = pk(h.x, h.y);
        RWu[r * KWS + d2] = pk(w.x, w.y);
    }
    __syncthreads();   // the ONLY block-wide barrier

    const float scale = 0.125f;

    // Key-tile split: octs 0-3 -> 4 tiles, octs 4-7 -> 3 tiles (28 total)
    const int ntile = (oct < 4) ? 4 : 3;
    const int tbase = (oct < 4) ? oct * 4 : 16 + (oct - 4) * 3;
    const uint32_t* Ru = (oct < 4) ? RHu : RWu;
    const int ecb = (oct & 3) * 8;

    // ldmatrix.trans base address into V (lane 0..15 -> rows, col n0=oct*8)
    const uint32_t vs_base =
        smem_u32(Vsu) + (uint32_t)((lane & 15) * KWS) * 4u + (uint32_t)oct * 16u;

#define BAR_MT() asm volatile("bar.sync %0, %1;" :: "r"(1 + mt), "r"(256) \
                              : "memory")

    for (int pass = 0; pass < 4; pass++) {
        const int q0 = pass * QT;

        // ---- QK^T (<=4 key-tiles/warp) + 1 rel-table tile/warp ----
        float s[4][4];
        float er[4];
#pragma unroll
        for (int j = 0; j < 4; j++)
#pragma unroll
            for (int q = 0; q < 4; q++) s[j][q] = 0.f;
#pragma unroll
        for (int q = 0; q < 4; q++) er[q] = 0.f;

#pragma unroll
        for (int ks = 0; ks < 4; ks++) {   // 64 dims = 4 x k16
            const int kb = ks * 8;
            uint32_t af[4];
            const int r = q0 + mt * 16 + g;
            af[0] = Qpu[r * KWS + kb + tg];
            af[1] = Qpu[(r + 8) * KWS + kb + tg];
            af[2] = Qpu[r * KWS + kb + tg + 4];
            af[3] = Qpu[(r + 8) * KWS + kb + tg + 4];
#pragma unroll
            for (int j = 0; j < 4; j++) {
                if (j < ntile) {
                    const int kn = (tbase + j) * 8;
                    uint32_t bf[2];
                    bf[0] = Ksu[(kn + g) * KWS + kb + tg];
                    bf[1] = Ksu[(kn + g) * KWS + kb + tg + 4];
                    mma_f16(s[j], af, bf);
                }
            }
            {
                const int rj = ecb + g;
                uint32_t bf[2];
                bf[0] = Ru[rj * KWS + kb + tg];
                bf[1] = Ru[rj * KWS + kb + tg + 4];
                mma_f16(er, af, bf);
            }
        }
#pragma unroll
        for (int j = 0; j < 4; j++) {
            if (j < ntile) {
                const int kn = (tbase + j) * 8;
                const int r = mt * 16 + g;
                *(float2*)&Ssm[r * SSF + kn + 2 * tg] =
                    make_float2(s[j][0], s[j][1]);
                *(float2*)&Ssm[(r + 8) * SSF + kn + 2 * tg] =
                    make_float2(s[j][2], s[j][3]);
            }
        }
        {
            float* Edst = (oct < 4) ? Eh : Ew;
            const int r = mt * 16 + g;
            const int col = ecb + 2 * tg;
            *(float2*)&Edst[r * ES + col] = make_float2(er[0], er[1]);
            *(float2*)&Edst[(r + 8) * ES + col] = make_float2(er[2], er[3]);
        }
        BAR_MT();   // S + E ready for this m-tile group

        // ---- softmax: 2 rows per warp ----
#pragma unroll
        for (int rr2 = 0; rr2 < 2; rr2++) {
            const int r = warp * 2 + rr2;       // local row, in group mt
            const int qt = q0 + r;
            if (qt < TOK) {
                const int qh = qt / WIN, qw = qt - WIN * (qt / WIN);
                const float* EhR = Eh + r * ES;
                const float* EwR = Ew + r * ES;
                float sv[7];
                float m = -1e30f;
#pragma unroll
                for (int j = 0; j < 7; j++) {
                    const int k = lane + 32 * j;
                    if (k < TOK) {
                        const int kh = k / WIN;
                        const int kw = k - WIN * kh;
                        sv[j] = Ssm[r * SSF + k] * scale
                              + EhR[qh - kh + 13]
                              + EwR[qw - kw + 13];
                    } else sv[j] = -1e30f;
                    m = fmaxf(m, sv[j]);
                }
#pragma unroll
                for (int off = 16; off > 0; off >>= 1)
                    m = fmaxf(m, __shfl_xor_sync(0xffffffffu, m, off));
                float p[7], sum = 0.f;
#pragma unroll
                for (int j = 0; j < 7; j++) {
                    const int k = lane + 32 * j;
                    p[j] = (k < TOK) ? __expf(sv[j] - m) : 0.f;
                    sum += p[j];
                }
#pragma unroll
                for (int off = 16; off > 0; off >>= 1)
                    sum += __shfl_xor_sync(0xffffffffu, sum, off);
                if (lane == 0) Sinv[r] = 1.f / sum;
#pragma unroll
                for (int j = 0; j < 7; j++)
                    Pbh[r * (2 * VWS) + lane + 32 * j] = __float2half_rn(p[j]);
            }
        }
        BAR_MT();   // P + Sinv ready for this m-tile group

        // ---- PV: 1 dim-tile/warp over 14 k16-chunks; V via ldmatrix.trans --
        float o[4];
#pragma unroll
        for (int q = 0; q < 4; q++) o[q] = 0.f;

#pragma unroll
        for (int ks = 0; ks < 14; ks++) {
            const int kb = ks * 8;
            uint32_t af[4];
            const int r = mt * 16 + g;
            af[0] = Pbu[r * VWS + kb + tg];
            af[1] = Pbu[(r + 8) * VWS + kb + tg];
            af[2] = Pbu[r * VWS + kb + tg + 4];
            af[3] = Pbu[(r + 8) * VWS + kb + tg + 4];
            uint32_t bf[2];
            ldsm_x2_t(bf[0], bf[1], vs_base + (uint32_t)(ks * 16 * KWS * 4));
            mma_f16(o, af, bf);
        }

        {
            const int qt0 = q0 + mt * 16 + g;
            const int qt1 = qt0 + 8;
            const float inv0 = (qt0 < TOK) ? Sinv[mt * 16 + g] : 0.f;
            const float inv1 = (qt1 < TOK) ? Sinv[mt * 16 + g + 8] : 0.f;
            const int d = oct * 8 + 2 * tg;
            if (qt0 < TOK) {
                __half* o0 = att_out + (size_t)(b * TOK + qt0) * HIDDEN
                           + head * HD + d;
                *(uint32_t*)o0 = pk(o[0] * inv0, o[1] * inv0);
            }
            if (qt1 < TOK) {
                __half* o1 = att_out + (size_t)(b * TOK + qt1) * HIDDEN
                           + head * HD + d;
                *(uint32_t*)o1 = pk(o[2] * inv1, o[3] * inv1);
            }
        }
        // no end-of-pass barrier needed: next-pass writes to Ssm/E are gated
        // by this pass's BAR #2, and next-pass writes to Pb/Sinv by next-pass
        // BAR #1 (all group warps have finished PV by then).
    }
#undef BAR_MT
}

// ---------------------------------------------------------------------------
extern "C" void kernel_launch(void* const* d_in, const int* in_sizes, int n_in,
                              void* d_out, int out_size) {
    const float* hidden = (const float*)d_in[0];
    const float* qkv_w  = (const float*)d_in[1];
    const float* qkv_b  = (const float*)d_in[2];
    const float* proj_w = (const float*)d_in[3];
    const float* proj_b = (const float*)d_in[4];
    const float* rel_h  = (const float*)d_in[5];
    const float* rel_w  = (const float*)d_in[6];
    float* out = (float*)d_out;

    void *p_qkv = nullptr, *p_att = nullptr, *p_hid = nullptr;
    void *p_wq = nullptr, *p_wp = nullptr;
    cudaGetSymbolAddress(&p_qkv, g_qkvh);
    cudaGetSymbolAddress(&p_att, g_atth);
    cudaGetSymbolAddress(&p_hid, g_hidh);
    cudaGetSymbolAddress(&p_wq, g_wqkvh);
    cudaGetSymbolAddress(&p_wp, g_wprjh);

    cudaFuncSetAttribute(attn_mma,
                         cudaFuncAttributeMaxDynamicSharedMemorySize,
                         ATT_SMEM_BYTES);

    // 0) fp32 -> fp16 pre-conversion (identical rounding to old staging)
    {
        const int nh = MTOK * HIDDEN;
        f2h<<<(nh / 8 + 255) / 256, 256>>>(hidden, (__half*)p_hid, nh);
        const int nq = NQKV * HIDDEN;
        f2h<<<(nq / 8 + 255) / 256, 256>>>(qkv_w, (__half*)p_wq, nq);
        const int np = HIDDEN * HIDDEN;
        f2h<<<(np / 8 + 255) / 256, 256>>>(proj_w, (__half*)p_wp, np);
    }

    // 1) QKV projection: fp16 x fp16 -> fp16
    gemm_hh<true><<<dim3(NQKV / 128, MTOK / 128), 256>>>(
        (const __half*)p_hid, (const __half*)p_wq, qkv_b, p_qkv,
        NQKV, HIDDEN);

    // 2) Attention (fp16 mma.sync; ldmatrix.trans V; grouped named barriers)
    attn_mma<<<BATCH * NHEADS, NTH, ATT_SMEM_BYTES>>>(
        (const __half*)p_qkv, rel_h, rel_w, (__half*)p_att);

    // 3) Output projection: fp16 x fp16 -> fp32
    gemm_hh<false><<<dim3(HIDDEN / 128, MTOK / 128), 256>>>(
        (const __half*)p_att, (const __half*)p_wp, proj_b, out,
        HIDDEN, HIDDEN);
}